// round 1
// baseline (speedup 1.0000x reference)
#include <cuda_runtime.h>
#include <math.h>

#define DIMC 384
#define NSEQ 1024
#define BATCH 16
#define BNTOT (BATCH*NSEQ)      /* 16384 rows */
#define NHEAD 6
#define HD 64
#define HIDDEN 1536
#define SCALE 0.125f            /* 64^-0.5 */
#define EPSV 1e-5f
#define APAD 68

/* ------------------------------------------------------------------ */
/* scratch (static device arrays: allocation-free per harness rules)  */
/* ------------------------------------------------------------------ */
__device__ float g_emb [2][BNTOT*DIMC];
__device__ float g_xn  [2][BNTOT*DIMC];
__device__ float g_kqv [2][BNTOT*3*DIMC];
__device__ float g_attn[2][BNTOT*DIMC];
__device__ float g_res [2][BNTOT*DIMC];
__device__ float g_h   [BNTOT*DIMC];
__device__ float g_gbuf[BNTOT*HIDDEN];

/* ------------------------------------------------------------------ */
/* K1: LayerNorm over channel dim + transpose [B,C,N] -> [B,N,C]      */
/* writes both emb (raw, transposed) and xn (normalized)              */
/* grid (N/32, B), block (32,8), dyn smem                             */
/* ------------------------------------------------------------------ */
#define LN_SMEM ((384*33 + 32 + 32 + 8*32*2) * 4)
__global__ void __launch_bounds__(256) ln_transpose_kernel(
    const float* __restrict__ x, const float* __restrict__ w,
    const float* __restrict__ bvec,
    float* __restrict__ emb, float* __restrict__ xn)
{
    extern __shared__ float sm[];
    float* tile  = sm;                 /* [384][33] */
    float* meanv = tile + 384*33;      /* [32] */
    float* rstdv = meanv + 32;         /* [32] */
    float* ps    = rstdv + 32;         /* [8][32] */
    float* pq    = ps + 8*32;          /* [8][32] */

    const int n0 = blockIdx.x * 32;
    const int b  = blockIdx.y;
    const int tx = threadIdx.x, ty = threadIdx.y;

    float s = 0.f, q = 0.f;
    for (int c = ty; c < DIMC; c += 8) {
        float v = x[(b*DIMC + c)*NSEQ + n0 + tx];
        tile[c*33 + tx] = v;
        s += v; q += v*v;
    }
    ps[ty*32+tx] = s; pq[ty*32+tx] = q;
    __syncthreads();
    if (ty == 0) {
        float S = 0.f, Q = 0.f;
        #pragma unroll
        for (int j = 0; j < 8; ++j) { S += ps[j*32+tx]; Q += pq[j*32+tx]; }
        float mu = S * (1.f/DIMC);
        meanv[tx] = mu;
        rstdv[tx] = rsqrtf(Q*(1.f/DIMC) - mu*mu + EPSV);
    }
    __syncthreads();
    const int tid  = ty*32 + tx;
    const int base = (b*NSEQ + n0)*DIMC;
    for (int idx = tid; idx < 32*DIMC; idx += 256) {
        int nl = idx / DIMC, c = idx - nl*DIMC;
        float v = tile[c*33 + nl];
        emb[base + idx] = v;
        xn [base + idx] = (v - meanv[nl]) * rstdv[nl] * w[c] + bvec[c];
    }
}

/* ------------------------------------------------------------------ */
/* K2: tiled SGEMM 128x128x16, 256 thr, 8x8/thread (split 4+4)        */
/* EPI: 0 = plain, 1 = +bias +residual, 2 = +bias then exact GELU     */
/* ------------------------------------------------------------------ */
__device__ __forceinline__ float gelu_f(float x) {
    return 0.5f * x * (1.f + erff(x * 0.7071067811865475f));
}

template<int EPI>
__global__ void __launch_bounds__(256) sgemm_kernel(
    const float* __restrict__ A, const float* __restrict__ B,
    const float* __restrict__ bias, const float* __restrict__ res,
    float* __restrict__ C, int M, int K, int N)
{
    __shared__ float As[16][132];
    __shared__ float Bs[16][128];
    const int bm = blockIdx.y * 128, bn = blockIdx.x * 128;
    const int tid = threadIdx.x;
    const int tx = tid & 15, ty = tid >> 4;

    float acc[8][8];
    #pragma unroll
    for (int i=0;i<8;++i)
        #pragma unroll
        for (int j=0;j<8;++j) acc[i][j]=0.f;

    const int arow = tid >> 1, ak = (tid & 1) * 8;
    const int brow = tid >> 5, bcol = (tid & 31) * 4;
    const float* Ap = A + (bm + arow)*K + ak;
    const float* Bp = B + brow*N + bn + bcol;

    for (int k0 = 0; k0 < K; k0 += 16) {
        float4 a0 = *(const float4*)(Ap + k0);
        float4 a1 = *(const float4*)(Ap + k0 + 4);
        float4 b0 = *(const float4*)(Bp + k0*N);
        float4 b1 = *(const float4*)(Bp + (k0+8)*N);
        As[ak+0][arow]=a0.x; As[ak+1][arow]=a0.y;
        As[ak+2][arow]=a0.z; As[ak+3][arow]=a0.w;
        As[ak+4][arow]=a1.x; As[ak+5][arow]=a1.y;
        As[ak+6][arow]=a1.z; As[ak+7][arow]=a1.w;
        *(float4*)&Bs[brow  ][bcol] = b0;
        *(float4*)&Bs[brow+8][bcol] = b1;
        __syncthreads();
        #pragma unroll
        for (int k = 0; k < 16; ++k) {
            float4 aA = *(float4*)&As[k][ty*4];
            float4 aB = *(float4*)&As[k][64+ty*4];
            float4 bA = *(float4*)&Bs[k][tx*4];
            float4 bB = *(float4*)&Bs[k][64+tx*4];
            float ar[8] = {aA.x,aA.y,aA.z,aA.w,aB.x,aB.y,aB.z,aB.w};
            float br[8] = {bA.x,bA.y,bA.z,bA.w,bB.x,bB.y,bB.z,bB.w};
            #pragma unroll
            for (int i=0;i<8;++i)
                #pragma unroll
                for (int j=0;j<8;++j)
                    acc[i][j] += ar[i]*br[j];
        }
        __syncthreads();
    }

    #pragma unroll
    for (int ih=0; ih<2; ++ih)
    #pragma unroll
    for (int i=0;i<4;++i) {
        int r = bm + ih*64 + ty*4 + i;
        #pragma unroll
        for (int jh=0;jh<2;++jh) {
            int c = bn + jh*64 + tx*4;
            float v0=acc[ih*4+i][jh*4+0], v1=acc[ih*4+i][jh*4+1];
            float v2=acc[ih*4+i][jh*4+2], v3=acc[ih*4+i][jh*4+3];
            if (EPI >= 1) {
                v0 += bias[c+0]; v1 += bias[c+1];
                v2 += bias[c+2]; v3 += bias[c+3];
            }
            if (EPI == 2) {
                v0 = gelu_f(v0); v1 = gelu_f(v1);
                v2 = gelu_f(v2); v3 = gelu_f(v3);
            }
            if (EPI == 1) {
                float4 rr = *(const float4*)(res + r*N + c);
                v0 += rr.x; v1 += rr.y; v2 += rr.z; v3 += rr.w;
            }
            float4 o = {v0,v1,v2,v3};
            *(float4*)(C + r*N + c) = o;
        }
    }
}

/* ------------------------------------------------------------------ */
/* K3: fp32 flash attention, Br=Bc=64, d=64. grid (16,6,16), 256 thr  */
/* q from kqvQ (+384 col), k/v from kqvKV (+0 / +768)                 */
/* ------------------------------------------------------------------ */
#define ATTN_SMEM ((4*64*APAD + 64*17) * 4)
__global__ void __launch_bounds__(256) attn_kernel(
    const float* __restrict__ kqvQ, const float* __restrict__ kqvKV,
    float* __restrict__ outp)
{
    extern __shared__ float sm[];
    float* Qs  = sm;                 /* [64][APAD] rows=q, cols=d */
    float* Kt  = Qs + 64*APAD;       /* [64][APAD] rows=d, cols=key */
    float* Vs  = Kt + 64*APAD;       /* [64][APAD] rows=key, cols=d */
    float* Ps  = Vs + 64*APAD;       /* [64][APAD] probs */
    float* red = Ps + 64*APAD;       /* [64][17]  reductions */

    const int qt = blockIdx.x, h = blockIdx.y, b = blockIdx.z;
    const int tid = threadIdx.x;
    const int tx = tid & 15, ty = tid >> 4;

    const float* qb = kqvQ  + (b*NSEQ + qt*64)*1152 + DIMC   + h*HD;
    const float* kb = kqvKV + (b*NSEQ)*1152                  + h*HD;
    const float* vb = kqvKV + (b*NSEQ)*1152 + 2*DIMC         + h*HD;

    for (int idx = tid; idx < 64*16; idx += 256) {
        int r = idx >> 4, f = (idx & 15) << 2;
        float4 v = *(const float4*)(qb + r*1152 + f);
        float4 sv = {v.x*SCALE, v.y*SCALE, v.z*SCALE, v.w*SCALE};
        *(float4*)(Qs + r*APAD + f) = sv;
    }

    float m[4], l[4], O[4][4];
    #pragma unroll
    for (int i=0;i<4;++i) {
        m[i] = -1e30f; l[i] = 0.f;
        #pragma unroll
        for (int u=0;u<4;++u) O[i][u]=0.f;
    }

    for (int t = 0; t < 16; ++t) {
        __syncthreads();   /* prev iter's Kt/Vs/Ps reads done (and Qs load on t=0) */
        for (int idx = tid; idx < 64*16; idx += 256) {
            int r = idx >> 4, f = (idx & 15) << 2;
            float4 kv = *(const float4*)(kb + (t*64 + r)*1152 + f);
            Kt[(f+0)*APAD + r] = kv.x;
            Kt[(f+1)*APAD + r] = kv.y;
            Kt[(f+2)*APAD + r] = kv.z;
            Kt[(f+3)*APAD + r] = kv.w;
            float4 vv = *(const float4*)(vb + (t*64 + r)*1152 + f);
            *(float4*)(Vs + r*APAD + f) = vv;
        }
        __syncthreads();

        /* S = (Q*scale) @ K^T : per-thread 4x4 */
        float S[4][4];
        #pragma unroll
        for (int i=0;i<4;++i)
            #pragma unroll
            for (int j=0;j<4;++j) S[i][j]=0.f;
        #pragma unroll 8
        for (int k=0;k<64;++k) {
            float4 kk = *(float4*)(Kt + k*APAD + tx*4);
            float a0 = Qs[(ty*4+0)*APAD + k];
            float a1 = Qs[(ty*4+1)*APAD + k];
            float a2 = Qs[(ty*4+2)*APAD + k];
            float a3 = Qs[(ty*4+3)*APAD + k];
            S[0][0]+=a0*kk.x; S[0][1]+=a0*kk.y; S[0][2]+=a0*kk.z; S[0][3]+=a0*kk.w;
            S[1][0]+=a1*kk.x; S[1][1]+=a1*kk.y; S[1][2]+=a1*kk.z; S[1][3]+=a1*kk.w;
            S[2][0]+=a2*kk.x; S[2][1]+=a2*kk.y; S[2][2]+=a2*kk.z; S[2][3]+=a2*kk.w;
            S[3][0]+=a3*kk.x; S[3][1]+=a3*kk.y; S[3][2]+=a3*kk.z; S[3][3]+=a3*kk.w;
        }

        /* online softmax: row max */
        #pragma unroll
        for (int i=0;i<4;++i) {
            float pm = fmaxf(fmaxf(S[i][0],S[i][1]), fmaxf(S[i][2],S[i][3]));
            red[(ty*4+i)*17 + tx] = pm;
        }
        __syncthreads();
        float mnew[4], alpha[4];
        #pragma unroll
        for (int i=0;i<4;++i) {
            int r = (ty*4+i)*17;
            float mt = red[r];
            #pragma unroll
            for (int j=1;j<16;++j) mt = fmaxf(mt, red[r+j]);
            mnew[i]  = fmaxf(m[i], mt);
            alpha[i] = __expf(m[i] - mnew[i]);
        }
        /* P = exp(S - mnew); partial row sums */
        float psum[4];
        #pragma unroll
        for (int i=0;i<4;++i) {
            float p0 = __expf(S[i][0]-mnew[i]);
            float p1 = __expf(S[i][1]-mnew[i]);
            float p2 = __expf(S[i][2]-mnew[i]);
            float p3 = __expf(S[i][3]-mnew[i]);
            psum[i] = p0+p1+p2+p3;
            float4 p4 = {p0,p1,p2,p3};
            *(float4*)(Ps + (ty*4+i)*APAD + tx*4) = p4;
        }
        __syncthreads();   /* red(max) reads done; Ps visible */
        #pragma unroll
        for (int i=0;i<4;++i) red[(ty*4+i)*17 + tx] = psum[i];
        __syncthreads();
        #pragma unroll
        for (int i=0;i<4;++i) {
            int r = (ty*4+i)*17;
            float sr = 0.f;
            #pragma unroll
            for (int j=0;j<16;++j) sr += red[r+j];
            l[i] = l[i]*alpha[i] + sr;
            m[i] = mnew[i];
            #pragma unroll
            for (int u=0;u<4;++u) O[i][u] *= alpha[i];
        }
        /* O += P @ V */
        #pragma unroll 8
        for (int j=0;j<64;++j) {
            float4 v4 = *(float4*)(Vs + j*APAD + tx*4);
            float p0 = Ps[(ty*4+0)*APAD + j];
            float p1 = Ps[(ty*4+1)*APAD + j];
            float p2 = Ps[(ty*4+2)*APAD + j];
            float p3 = Ps[(ty*4+3)*APAD + j];
            O[0][0]+=p0*v4.x; O[0][1]+=p0*v4.y; O[0][2]+=p0*v4.z; O[0][3]+=p0*v4.w;
            O[1][0]+=p1*v4.x; O[1][1]+=p1*v4.y; O[1][2]+=p1*v4.z; O[1][3]+=p1*v4.w;
            O[2][0]+=p2*v4.x; O[2][1]+=p2*v4.y; O[2][2]+=p2*v4.z; O[2][3]+=p2*v4.w;
            O[3][0]+=p3*v4.x; O[3][1]+=p3*v4.y; O[3][2]+=p3*v4.z; O[3][3]+=p3*v4.w;
        }
    }

    #pragma unroll
    for (int i=0;i<4;++i) {
        float inv = 1.f / l[i];
        int r = b*NSEQ + qt*64 + ty*4 + i;
        float4 o = {O[i][0]*inv, O[i][1]*inv, O[i][2]*inv, O[i][3]*inv};
        *(float4*)(outp + r*DIMC + h*HD + tx*4) = o;
    }
}

/* ------------------------------------------------------------------ */
/* K4: row LayerNorm over last (contiguous) dim of 384                */
/* ------------------------------------------------------------------ */
__global__ void __launch_bounds__(128) ln_rows_kernel(
    const float* __restrict__ in, const float* __restrict__ w,
    const float* __restrict__ bb, float* __restrict__ out)
{
    const int row = blockIdx.x;
    const float* p = in + row*DIMC;
    const int tid = threadIdx.x;
    float v0 = p[tid], v1 = p[tid+128], v2 = p[tid+256];
    float s = v0+v1+v2;
    float q = v0*v0 + v1*v1 + v2*v2;
    #pragma unroll
    for (int o = 16; o; o >>= 1) {
        s += __shfl_xor_sync(0xffffffffu, s, o);
        q += __shfl_xor_sync(0xffffffffu, q, o);
    }
    __shared__ float ss[4], qq[4];
    if ((tid & 31) == 0) { ss[tid>>5] = s; qq[tid>>5] = q; }
    __syncthreads();
    s = ss[0]+ss[1]+ss[2]+ss[3];
    q = qq[0]+qq[1]+qq[2]+qq[3];
    float mu = s * (1.f/DIMC);
    float rs = rsqrtf(q*(1.f/DIMC) - mu*mu + EPSV);
    out[row*DIMC + tid      ] = (v0-mu)*rs*w[tid      ] + bb[tid      ];
    out[row*DIMC + tid + 128] = (v1-mu)*rs*w[tid + 128] + bb[tid + 128];
    out[row*DIMC + tid + 256] = (v2-mu)*rs*w[tid + 256] + bb[tid + 256];
}

/* ------------------------------------------------------------------ */
/* K5: transpose [B,N,C] -> [B,C,N] into d_out                        */
/* ------------------------------------------------------------------ */
__global__ void __launch_bounds__(256) transpose_out_kernel(
    const float* __restrict__ in, float* __restrict__ outp)
{
    __shared__ float t[32][33];
    const int n0 = blockIdx.x*32, c0 = blockIdx.y*32, b = blockIdx.z;
    const int tx = threadIdx.x, ty = threadIdx.y;
    #pragma unroll
    for (int i = ty; i < 32; i += 8)
        t[i][tx] = in[(b*NSEQ + n0+i)*DIMC + c0 + tx];
    __syncthreads();
    #pragma unroll
    for (int i = ty; i < 32; i += 8)
        outp[(b*DIMC + c0+i)*NSEQ + n0 + tx] = t[tx][i];
}

/* ------------------------------------------------------------------ */
extern "C" void kernel_launch(void* const* d_in, const int* in_sizes, int n_in,
                              void* d_out, int out_size)
{
    (void)in_sizes; (void)n_in; (void)out_size;
    const float* x1       = (const float*)d_in[0];
    const float* x2       = (const float*)d_in[1];
    const float* ln_a1_w  = (const float*)d_in[2];
    const float* ln_a1_b  = (const float*)d_in[3];
    const float* kqv1_w   = (const float*)d_in[4];
    const float* ln_a2_w  = (const float*)d_in[5];
    const float* ln_a2_b  = (const float*)d_in[6];
    const float* kqv2_w   = (const float*)d_in[7];
    const float* proj1_w  = (const float*)d_in[8];
    const float* proj1_b  = (const float*)d_in[9];
    const float* proj2_w  = (const float*)d_in[10];
    const float* proj2_b  = (const float*)d_in[11];
    const float* ln1_w    = (const float*)d_in[12];
    const float* ln1_b    = (const float*)d_in[13];
    const float* ln2_w    = (const float*)d_in[14];
    const float* ln2_b    = (const float*)d_in[15];
    const float* m1f1_w   = (const float*)d_in[16];
    const float* m1f1_b   = (const float*)d_in[17];
    const float* m1f2_w   = (const float*)d_in[18];
    const float* m1f2_b   = (const float*)d_in[19];
    const float* m2f1_w   = (const float*)d_in[20];
    const float* m2f1_b   = (const float*)d_in[21];
    const float* m2f2_w   = (const float*)d_in[22];
    const float* m2f2_b   = (const float*)d_in[23];
    float* outp = (float*)d_out;

    float *p_emb, *p_xn, *p_kqv, *p_attn, *p_res, *p_h, *p_g;
    cudaGetSymbolAddress((void**)&p_emb,  g_emb);
    cudaGetSymbolAddress((void**)&p_xn,   g_xn);
    cudaGetSymbolAddress((void**)&p_kqv,  g_kqv);
    cudaGetSymbolAddress((void**)&p_attn, g_attn);
    cudaGetSymbolAddress((void**)&p_res,  g_res);
    cudaGetSymbolAddress((void**)&p_h,    g_h);
    cudaGetSymbolAddress((void**)&p_g,    g_gbuf);

    cudaFuncSetAttribute(ln_transpose_kernel,
        cudaFuncAttributeMaxDynamicSharedMemorySize, LN_SMEM);
    cudaFuncSetAttribute(attn_kernel,
        cudaFuncAttributeMaxDynamicSharedMemorySize, ATTN_SMEM);

    const int OFF  = BNTOT*DIMC;
    const int KOFF = BNTOT*3*DIMC;
    const dim3 lnb(32, 8);

    /* embeddings + pre-attention LN (transposed layout) */
    ln_transpose_kernel<<<dim3(32,16), lnb, LN_SMEM>>>(x1, ln_a1_w, ln_a1_b, p_emb,     p_xn);
    ln_transpose_kernel<<<dim3(32,16), lnb, LN_SMEM>>>(x2, ln_a2_w, ln_a2_b, p_emb+OFF, p_xn+OFF);

    /* kqv projections: [16384,384]@[384,1152] */
    sgemm_kernel<0><<<dim3(9,128), 256>>>(p_xn,     kqv1_w, nullptr, nullptr, p_kqv,      BNTOT, DIMC, 3*DIMC);
    sgemm_kernel<0><<<dim3(9,128), 256>>>(p_xn+OFF, kqv2_w, nullptr, nullptr, p_kqv+KOFF, BNTOT, DIMC, 3*DIMC);

    /* cross attention: branch1 queries attend to branch2 kv, and vice versa */
    attn_kernel<<<dim3(16,6,16), 256, ATTN_SMEM>>>(p_kqv,      p_kqv+KOFF, p_attn);
    attn_kernel<<<dim3(16,6,16), 256, ATTN_SMEM>>>(p_kqv+KOFF, p_kqv,      p_attn+OFF);

    /* branch 1: proj(+emb residual), LN, fc1+gelu, fc2(+residual), transpose */
    sgemm_kernel<1><<<dim3(3,128),  256>>>(p_attn, proj1_w, proj1_b, p_emb, p_res, BNTOT, DIMC, DIMC);
    ln_rows_kernel<<<BNTOT, 128>>>(p_res, ln1_w, ln1_b, p_h);
    sgemm_kernel<2><<<dim3(12,128), 256>>>(p_h, m1f1_w, m1f1_b, nullptr, p_g, BNTOT, DIMC, HIDDEN);
    sgemm_kernel<1><<<dim3(3,128),  256>>>(p_g, m1f2_w, m1f2_b, p_res, p_res, BNTOT, HIDDEN, DIMC);
    transpose_out_kernel<<<dim3(32,12,16), lnb>>>(p_res, outp);

    /* branch 2 */
    sgemm_kernel<1><<<dim3(3,128),  256>>>(p_attn+OFF, proj2_w, proj2_b, p_emb+OFF, p_res+OFF, BNTOT, DIMC, DIMC);
    ln_rows_kernel<<<BNTOT, 128>>>(p_res+OFF, ln2_w, ln2_b, p_h);
    sgemm_kernel<2><<<dim3(12,128), 256>>>(p_h, m2f1_w, m2f1_b, nullptr, p_g, BNTOT, DIMC, HIDDEN);
    sgemm_kernel<1><<<dim3(3,128),  256>>>(p_g, m2f2_w, m2f2_b, p_res+OFF, p_res+OFF, BNTOT, HIDDEN, DIMC);
    transpose_out_kernel<<<dim3(32,12,16), lnb>>>(p_res+OFF, outp + OFF);
}

// round 2
// speedup vs baseline: 1.6044x; 1.6044x over previous
#include <cuda_runtime.h>
#include <cuda_bf16.h>
#include <math.h>
#include <stdint.h>

#define DIMC 384
#define NSEQ 1024
#define BATCH 16
#define BNTOT (BATCH*NSEQ)      /* 16384 rows */
#define NHEAD 6
#define HD 64
#define HIDDEN 1536
#define SCALE 0.125f            /* 64^-0.5 */
#define EPSV 1e-5f
#define APAD 68

/* ------------------------------------------------------------------ */
/* scratch                                                             */
/* ------------------------------------------------------------------ */
__device__ float g_emb [2][BNTOT*DIMC];
__device__ float g_xn  [2][BNTOT*DIMC];
__device__ float g_kqv [2][BNTOT*3*DIMC];
__device__ float g_attn[2][BNTOT*DIMC];
__device__ float g_res [2][BNTOT*DIMC];
__device__ float g_h   [BNTOT*DIMC];
__device__ float g_gbuf[BNTOT*HIDDEN];

/* ------------------------------------------------------------------ */
/* K1: LayerNorm over channel dim + transpose [B,C,N] -> [B,N,C]      */
/* ------------------------------------------------------------------ */
#define LN_SMEM ((384*33 + 32 + 32 + 8*32*2) * 4)
__global__ void __launch_bounds__(256) ln_transpose_kernel(
    const float* __restrict__ x, const float* __restrict__ w,
    const float* __restrict__ bvec,
    float* __restrict__ emb, float* __restrict__ xn)
{
    extern __shared__ float sm[];
    float* tile  = sm;
    float* meanv = tile + 384*33;
    float* rstdv = meanv + 32;
    float* ps    = rstdv + 32;
    float* pq    = ps + 8*32;

    const int n0 = blockIdx.x * 32;
    const int b  = blockIdx.y;
    const int tx = threadIdx.x, ty = threadIdx.y;

    float s = 0.f, q = 0.f;
    for (int c = ty; c < DIMC; c += 8) {
        float v = x[(b*DIMC + c)*NSEQ + n0 + tx];
        tile[c*33 + tx] = v;
        s += v; q += v*v;
    }
    ps[ty*32+tx] = s; pq[ty*32+tx] = q;
    __syncthreads();
    if (ty == 0) {
        float S = 0.f, Q = 0.f;
        #pragma unroll
        for (int j = 0; j < 8; ++j) { S += ps[j*32+tx]; Q += pq[j*32+tx]; }
        float mu = S * (1.f/DIMC);
        meanv[tx] = mu;
        rstdv[tx] = rsqrtf(Q*(1.f/DIMC) - mu*mu + EPSV);
    }
    __syncthreads();
    const int tid  = ty*32 + tx;
    const int base = (b*NSEQ + n0)*DIMC;
    for (int idx = tid; idx < 32*DIMC; idx += 256) {
        int nl = idx / DIMC, c = idx - nl*DIMC;
        float v = tile[c*33 + nl];
        emb[base + idx] = v;
        xn [base + idx] = (v - meanv[nl]) * rstdv[nl] * w[c] + bvec[c];
    }
}

/* ------------------------------------------------------------------ */
/* K2: bf16 tensor-core GEMM 128x128x32, mma.sync m16n8k16            */
/* 256 thr = 8 warps (2x4), warp tile 64x32. fp32 in/out, bf16 mma.   */
/* EPI: 0 plain, 1 +bias+residual, 2 +bias then exact GELU            */
/* ------------------------------------------------------------------ */
__device__ __forceinline__ float gelu_f(float x) {
    return 0.5f * x * (1.f + erff(x * 0.7071067811865475f));
}

#define ALD 40    /* A smem row stride (bf16 elems), conflict-free for ldmatrix */
#define BLD 136   /* B smem row stride */

__device__ __forceinline__ uint32_t smem_u32(const void* p) {
    return (uint32_t)__cvta_generic_to_shared(p);
}

__device__ __forceinline__ void ldm_x4(uint32_t* r, uint32_t addr) {
    asm volatile("ldmatrix.sync.aligned.m8n8.x4.shared.b16 {%0,%1,%2,%3}, [%4];"
        : "=r"(r[0]), "=r"(r[1]), "=r"(r[2]), "=r"(r[3]) : "r"(addr));
}
__device__ __forceinline__ void ldm_x4_t(uint32_t* r, uint32_t addr) {
    asm volatile("ldmatrix.sync.aligned.m8n8.x4.trans.shared.b16 {%0,%1,%2,%3}, [%4];"
        : "=r"(r[0]), "=r"(r[1]), "=r"(r[2]), "=r"(r[3]) : "r"(addr));
}
__device__ __forceinline__ void mma_bf16(float* d, const uint32_t* a, const uint32_t* b) {
    asm volatile(
        "mma.sync.aligned.m16n8k16.row.col.f32.bf16.bf16.f32 "
        "{%0,%1,%2,%3}, {%4,%5,%6,%7}, {%8,%9}, {%0,%1,%2,%3};"
        : "+f"(d[0]), "+f"(d[1]), "+f"(d[2]), "+f"(d[3])
        : "r"(a[0]), "r"(a[1]), "r"(a[2]), "r"(a[3]), "r"(b[0]), "r"(b[1]));
}

template<int EPI>
__global__ void __launch_bounds__(256) hgemm_kernel(
    const float* __restrict__ A, const float* __restrict__ B,
    const float* __restrict__ bias, const float* __restrict__ res,
    float* __restrict__ C, int M, int K, int N)
{
    __shared__ __nv_bfloat16 As[2][128*ALD];
    __shared__ __nv_bfloat16 Bs[2][32*BLD];

    const int bm = blockIdx.y * 128, bn = blockIdx.x * 128;
    const int tid  = threadIdx.x;
    const int lane = tid & 31, wid = tid >> 5;
    const int wm = wid & 1, wn = wid >> 1;   /* 2x4 warp grid */

    /* global load mapping */
    const int arow = tid >> 1, acol = (tid & 1) * 16;
    const int brow = tid >> 3, bcol = (tid & 7) * 16;
    const float* Ag = A + (size_t)(bm + arow)*K + acol;
    const float* Bg = B + (size_t)brow*N + bn + bcol;

    float4 ar[4], br[4];
    const int nch = K >> 5;

    /* load chunk 0 */
    #pragma unroll
    for (int i = 0; i < 4; ++i) ar[i] = *(const float4*)(Ag + i*4);
    #pragma unroll
    for (int i = 0; i < 4; ++i) br[i] = *(const float4*)(Bg + i*4);

    auto store_smem = [&](int buf) {
        __nv_bfloat16* ap = &As[buf][arow*ALD + acol];
        __nv_bfloat16* bp = &Bs[buf][brow*BLD + bcol];
        #pragma unroll
        for (int i = 0; i < 4; ++i) {
            *(__nv_bfloat162*)(ap + i*4    ) = __float22bfloat162_rn({ar[i].x, ar[i].y});
            *(__nv_bfloat162*)(ap + i*4 + 2) = __float22bfloat162_rn({ar[i].z, ar[i].w});
            *(__nv_bfloat162*)(bp + i*4    ) = __float22bfloat162_rn({br[i].x, br[i].y});
            *(__nv_bfloat162*)(bp + i*4 + 2) = __float22bfloat162_rn({br[i].z, br[i].w});
        }
    };
    store_smem(0);
    __syncthreads();

    float acc[4][4][4];
    #pragma unroll
    for (int i=0;i<4;++i)
        #pragma unroll
        for (int j=0;j<4;++j)
            #pragma unroll
            for (int u=0;u<4;++u) acc[i][j][u]=0.f;

    /* ldmatrix lane addressing */
    const int a_r = (lane & 15), a_c8 = (lane >> 4) * 8;
    const int b_k = (lane & 15), b_n8 = (lane >> 4) * 8;

    for (int c = 0; c < nch; ++c) {
        const int buf = c & 1;
        if (c + 1 < nch) {
            const float* Agn = Ag + (c+1)*32;
            const float* Bgn = Bg + (size_t)(c+1)*32*N;
            #pragma unroll
            for (int i = 0; i < 4; ++i) ar[i] = *(const float4*)(Agn + i*4);
            #pragma unroll
            for (int i = 0; i < 4; ++i) br[i] = *(const float4*)(Bgn + i*4);
        }

        #pragma unroll
        for (int ks = 0; ks < 2; ++ks) {
            uint32_t af[4][4], bf[4][2];
            #pragma unroll
            for (int mt = 0; mt < 4; ++mt) {
                int row = wm*64 + mt*16 + a_r;
                int col = ks*16 + a_c8;
                ldm_x4(af[mt], smem_u32(&As[buf][row*ALD + col]));
            }
            #pragma unroll
            for (int np = 0; np < 2; ++np) {
                uint32_t rr[4];
                int kk = ks*16 + b_k;
                int nn = wn*32 + np*16 + b_n8;
                ldm_x4_t(rr, smem_u32(&Bs[buf][kk*BLD + nn]));
                bf[np*2  ][0]=rr[0]; bf[np*2  ][1]=rr[1];
                bf[np*2+1][0]=rr[2]; bf[np*2+1][1]=rr[3];
            }
            #pragma unroll
            for (int mt = 0; mt < 4; ++mt)
                #pragma unroll
                for (int nt = 0; nt < 4; ++nt)
                    mma_bf16(acc[mt][nt], af[mt], bf[nt]);
        }
        __syncthreads();
        if (c + 1 < nch) {
            store_smem((c+1) & 1);
            __syncthreads();
        }
    }

    /* epilogue: thread holds (g,2q),(g,2q+1),(g+8,2q),(g+8,2q+1) per tile */
    const int g = lane >> 2, qp = lane & 3;
    #pragma unroll
    for (int mt = 0; mt < 4; ++mt) {
        #pragma unroll
        for (int half = 0; half < 2; ++half) {
            int r = bm + wm*64 + mt*16 + g + half*8;
            #pragma unroll
            for (int nt = 0; nt < 4; ++nt) {
                int cix = bn + wn*32 + nt*8 + qp*2;
                float v0 = acc[mt][nt][half*2+0];
                float v1 = acc[mt][nt][half*2+1];
                if (EPI >= 1) { v0 += bias[cix]; v1 += bias[cix+1]; }
                if (EPI == 2) { v0 = gelu_f(v0); v1 = gelu_f(v1); }
                if (EPI == 1) {
                    float2 rr = *(const float2*)(res + (size_t)r*N + cix);
                    v0 += rr.x; v1 += rr.y;
                }
                float2 o = {v0, v1};
                *(float2*)(C + (size_t)r*N + cix) = o;
            }
        }
    }
}

/* ------------------------------------------------------------------ */
/* K3: fp32 flash attention (unchanged this round)                    */
/* ------------------------------------------------------------------ */
#define ATTN_SMEM ((4*64*APAD + 64*17) * 4)
__global__ void __launch_bounds__(256) attn_kernel(
    const float* __restrict__ kqvQ, const float* __restrict__ kqvKV,
    float* __restrict__ outp)
{
    extern __shared__ float sm[];
    float* Qs  = sm;
    float* Kt  = Qs + 64*APAD;
    float* Vs  = Kt + 64*APAD;
    float* Ps  = Vs + 64*APAD;
    float* red = Ps + 64*APAD;

    const int qt = blockIdx.x, h = blockIdx.y, b = blockIdx.z;
    const int tid = threadIdx.x;
    const int tx = tid & 15, ty = tid >> 4;

    const float* qb = kqvQ  + (b*NSEQ + qt*64)*1152 + DIMC   + h*HD;
    const float* kb = kqvKV + (b*NSEQ)*1152                  + h*HD;
    const float* vb = kqvKV + (b*NSEQ)*1152 + 2*DIMC         + h*HD;

    for (int idx = tid; idx < 64*16; idx += 256) {
        int r = idx >> 4, f = (idx & 15) << 2;
        float4 v = *(const float4*)(qb + r*1152 + f);
        float4 sv = {v.x*SCALE, v.y*SCALE, v.z*SCALE, v.w*SCALE};
        *(float4*)(Qs + r*APAD + f) = sv;
    }

    float m[4], l[4], O[4][4];
    #pragma unroll
    for (int i=0;i<4;++i) {
        m[i] = -1e30f; l[i] = 0.f;
        #pragma unroll
        for (int u=0;u<4;++u) O[i][u]=0.f;
    }

    for (int t = 0; t < 16; ++t) {
        __syncthreads();
        for (int idx = tid; idx < 64*16; idx += 256) {
            int r = idx >> 4, f = (idx & 15) << 2;
            float4 kv = *(const float4*)(kb + (t*64 + r)*1152 + f);
            Kt[(f+0)*APAD + r] = kv.x;
            Kt[(f+1)*APAD + r] = kv.y;
            Kt[(f+2)*APAD + r] = kv.z;
            Kt[(f+3)*APAD + r] = kv.w;
            float4 vv = *(const float4*)(vb + (t*64 + r)*1152 + f);
            *(float4*)(Vs + r*APAD + f) = vv;
        }
        __syncthreads();

        float S[4][4];
        #pragma unroll
        for (int i=0;i<4;++i)
            #pragma unroll
            for (int j=0;j<4;++j) S[i][j]=0.f;
        #pragma unroll 8
        for (int k=0;k<64;++k) {
            float4 kk = *(float4*)(Kt + k*APAD + tx*4);
            float a0 = Qs[(ty*4+0)*APAD + k];
            float a1 = Qs[(ty*4+1)*APAD + k];
            float a2 = Qs[(ty*4+2)*APAD + k];
            float a3 = Qs[(ty*4+3)*APAD + k];
            S[0][0]+=a0*kk.x; S[0][1]+=a0*kk.y; S[0][2]+=a0*kk.z; S[0][3]+=a0*kk.w;
            S[1][0]+=a1*kk.x; S[1][1]+=a1*kk.y; S[1][2]+=a1*kk.z; S[1][3]+=a1*kk.w;
            S[2][0]+=a2*kk.x; S[2][1]+=a2*kk.y; S[2][2]+=a2*kk.z; S[2][3]+=a2*kk.w;
            S[3][0]+=a3*kk.x; S[3][1]+=a3*kk.y; S[3][2]+=a3*kk.z; S[3][3]+=a3*kk.w;
        }

        #pragma unroll
        for (int i=0;i<4;++i) {
            float pm = fmaxf(fmaxf(S[i][0],S[i][1]), fmaxf(S[i][2],S[i][3]));
            red[(ty*4+i)*17 + tx] = pm;
        }
        __syncthreads();
        float mnew[4], alpha[4];
        #pragma unroll
        for (int i=0;i<4;++i) {
            int r = (ty*4+i)*17;
            float mt = red[r];
            #pragma unroll
            for (int j=1;j<16;++j) mt = fmaxf(mt, red[r+j]);
            mnew[i]  = fmaxf(m[i], mt);
            alpha[i] = __expf(m[i] - mnew[i]);
        }
        float psum[4];
        #pragma unroll
        for (int i=0;i<4;++i) {
            float p0 = __expf(S[i][0]-mnew[i]);
            float p1 = __expf(S[i][1]-mnew[i]);
            float p2 = __expf(S[i][2]-mnew[i]);
            float p3 = __expf(S[i][3]-mnew[i]);
            psum[i] = p0+p1+p2+p3;
            float4 p4 = {p0,p1,p2,p3};
            *(float4*)(Ps + (ty*4+i)*APAD + tx*4) = p4;
        }
        __syncthreads();
        #pragma unroll
        for (int i=0;i<4;++i) red[(ty*4+i)*17 + tx] = psum[i];
        __syncthreads();
        #pragma unroll
        for (int i=0;i<4;++i) {
            int r = (ty*4+i)*17;
            float sr = 0.f;
            #pragma unroll
            for (int j=0;j<16;++j) sr += red[r+j];
            l[i] = l[i]*alpha[i] + sr;
            m[i] = mnew[i];
            #pragma unroll
            for (int u=0;u<4;++u) O[i][u] *= alpha[i];
        }
        #pragma unroll 8
        for (int j=0;j<64;++j) {
            float4 v4 = *(float4*)(Vs + j*APAD + tx*4);
            float p0 = Ps[(ty*4+0)*APAD + j];
            float p1 = Ps[(ty*4+1)*APAD + j];
            float p2 = Ps[(ty*4+2)*APAD + j];
            float p3 = Ps[(ty*4+3)*APAD + j];
            O[0][0]+=p0*v4.x; O[0][1]+=p0*v4.y; O[0][2]+=p0*v4.z; O[0][3]+=p0*v4.w;
            O[1][0]+=p1*v4.x; O[1][1]+=p1*v4.y; O[1][2]+=p1*v4.z; O[1][3]+=p1*v4.w;
            O[2][0]+=p2*v4.x; O[2][1]+=p2*v4.y; O[2][2]+=p2*v4.z; O[2][3]+=p2*v4.w;
            O[3][0]+=p3*v4.x; O[3][1]+=p3*v4.y; O[3][2]+=p3*v4.z; O[3][3]+=p3*v4.w;
        }
    }

    #pragma unroll
    for (int i=0;i<4;++i) {
        float inv = 1.f / l[i];
        int r = b*NSEQ + qt*64 + ty*4 + i;
        float4 o = {O[i][0]*inv, O[i][1]*inv, O[i][2]*inv, O[i][3]*inv};
        *(float4*)(outp + r*DIMC + h*HD + tx*4) = o;
    }
}

/* ------------------------------------------------------------------ */
/* K4: row LayerNorm over last dim 384                                */
/* ------------------------------------------------------------------ */
__global__ void __launch_bounds__(128) ln_rows_kernel(
    const float* __restrict__ in, const float* __restrict__ w,
    const float* __restrict__ bb, float* __restrict__ out)
{
    const int row = blockIdx.x;
    const float* p = in + row*DIMC;
    const int tid = threadIdx.x;
    float v0 = p[tid], v1 = p[tid+128], v2 = p[tid+256];
    float s = v0+v1+v2;
    float q = v0*v0 + v1*v1 + v2*v2;
    #pragma unroll
    for (int o = 16; o; o >>= 1) {
        s += __shfl_xor_sync(0xffffffffu, s, o);
        q += __shfl_xor_sync(0xffffffffu, q, o);
    }
    __shared__ float ss[4], qq[4];
    if ((tid & 31) == 0) { ss[tid>>5] = s; qq[tid>>5] = q; }
    __syncthreads();
    s = ss[0]+ss[1]+ss[2]+ss[3];
    q = qq[0]+qq[1]+qq[2]+qq[3];
    float mu = s * (1.f/DIMC);
    float rs = rsqrtf(q*(1.f/DIMC) - mu*mu + EPSV);
    out[row*DIMC + tid      ] = (v0-mu)*rs*w[tid      ] + bb[tid      ];
    out[row*DIMC + tid + 128] = (v1-mu)*rs*w[tid + 128] + bb[tid + 128];
    out[row*DIMC + tid + 256] = (v2-mu)*rs*w[tid + 256] + bb[tid + 256];
}

/* ------------------------------------------------------------------ */
/* K5: transpose [B,N,C] -> [B,C,N] into d_out                        */
/* ------------------------------------------------------------------ */
__global__ void __launch_bounds__(256) transpose_out_kernel(
    const float* __restrict__ in, float* __restrict__ outp)
{
    __shared__ float t[32][33];
    const int n0 = blockIdx.x*32, c0 = blockIdx.y*32, b = blockIdx.z;
    const int tx = threadIdx.x, ty = threadIdx.y;
    #pragma unroll
    for (int i = ty; i < 32; i += 8)
        t[i][tx] = in[(b*NSEQ + n0+i)*DIMC + c0 + tx];
    __syncthreads();
    #pragma unroll
    for (int i = ty; i < 32; i += 8)
        outp[(b*DIMC + c0+i)*NSEQ + n0 + tx] = t[tx][i];
}

/* ------------------------------------------------------------------ */
extern "C" void kernel_launch(void* const* d_in, const int* in_sizes, int n_in,
                              void* d_out, int out_size)
{
    (void)in_sizes; (void)n_in; (void)out_size;
    const float* x1       = (const float*)d_in[0];
    const float* x2       = (const float*)d_in[1];
    const float* ln_a1_w  = (const float*)d_in[2];
    const float* ln_a1_b  = (const float*)d_in[3];
    const float* kqv1_w   = (const float*)d_in[4];
    const float* ln_a2_w  = (const float*)d_in[5];
    const float* ln_a2_b  = (const float*)d_in[6];
    const float* kqv2_w   = (const float*)d_in[7];
    const float* proj1_w  = (const float*)d_in[8];
    const float* proj1_b  = (const float*)d_in[9];
    const float* proj2_w  = (const float*)d_in[10];
    const float* proj2_b  = (const float*)d_in[11];
    const float* ln1_w    = (const float*)d_in[12];
    const float* ln1_b    = (const float*)d_in[13];
    const float* ln2_w    = (const float*)d_in[14];
    const float* ln2_b    = (const float*)d_in[15];
    const float* m1f1_w   = (const float*)d_in[16];
    const float* m1f1_b   = (const float*)d_in[17];
    const float* m1f2_w   = (const float*)d_in[18];
    const float* m1f2_b   = (const float*)d_in[19];
    const float* m2f1_w   = (const float*)d_in[20];
    const float* m2f1_b   = (const float*)d_in[21];
    const float* m2f2_w   = (const float*)d_in[22];
    const float* m2f2_b   = (const float*)d_in[23];
    float* outp = (float*)d_out;

    float *p_emb, *p_xn, *p_kqv, *p_attn, *p_res, *p_h, *p_g;
    cudaGetSymbolAddress((void**)&p_emb,  g_emb);
    cudaGetSymbolAddress((void**)&p_xn,   g_xn);
    cudaGetSymbolAddress((void**)&p_kqv,  g_kqv);
    cudaGetSymbolAddress((void**)&p_attn, g_attn);
    cudaGetSymbolAddress((void**)&p_res,  g_res);
    cudaGetSymbolAddress((void**)&p_h,    g_h);
    cudaGetSymbolAddress((void**)&p_g,    g_gbuf);

    cudaFuncSetAttribute(ln_transpose_kernel,
        cudaFuncAttributeMaxDynamicSharedMemorySize, LN_SMEM);
    cudaFuncSetAttribute(attn_kernel,
        cudaFuncAttributeMaxDynamicSharedMemorySize, ATTN_SMEM);

    const int OFF  = BNTOT*DIMC;
    const int KOFF = BNTOT*3*DIMC;
    const dim3 lnb(32, 8);

    ln_transpose_kernel<<<dim3(32,16), lnb, LN_SMEM>>>(x1, ln_a1_w, ln_a1_b, p_emb,     p_xn);
    ln_transpose_kernel<<<dim3(32,16), lnb, LN_SMEM>>>(x2, ln_a2_w, ln_a2_b, p_emb+OFF, p_xn+OFF);

    hgemm_kernel<0><<<dim3(9,128),  256>>>(p_xn,     kqv1_w, nullptr, nullptr, p_kqv,      BNTOT, DIMC, 3*DIMC);
    hgemm_kernel<0><<<dim3(9,128),  256>>>(p_xn+OFF, kqv2_w, nullptr, nullptr, p_kqv+KOFF, BNTOT, DIMC, 3*DIMC);

    attn_kernel<<<dim3(16,6,16), 256, ATTN_SMEM>>>(p_kqv,      p_kqv+KOFF, p_attn);
    attn_kernel<<<dim3(16,6,16), 256, ATTN_SMEM>>>(p_kqv+KOFF, p_kqv,      p_attn+OFF);

    hgemm_kernel<1><<<dim3(3,128),  256>>>(p_attn, proj1_w, proj1_b, p_emb, p_res, BNTOT, DIMC, DIMC);
    ln_rows_kernel<<<BNTOT, 128>>>(p_res, ln1_w, ln1_b, p_h);
    hgemm_kernel<2><<<dim3(12,128), 256>>>(p_h, m1f1_w, m1f1_b, nullptr, p_g, BNTOT, DIMC, HIDDEN);
    hgemm_kernel<1><<<dim3(3,128),  256>>>(p_g, m1f2_w, m1f2_b, p_res, p_res, BNTOT, HIDDEN, DIMC);
    transpose_out_kernel<<<dim3(32,12,16), lnb>>>(p_res, outp);

    hgemm_kernel<1><<<dim3(3,128),  256>>>(p_attn+OFF, proj2_w, proj2_b, p_emb+OFF, p_res+OFF, BNTOT, DIMC, DIMC);
    ln_rows_kernel<<<BNTOT, 128>>>(p_res+OFF, ln2_w, ln2_b, p_h);
    hgemm_kernel<2><<<dim3(12,128), 256>>>(p_h, m2f1_w, m2f1_b, nullptr, p_g, BNTOT, DIMC, HIDDEN);
    hgemm_kernel<1><<<dim3(3,128),  256>>>(p_g, m2f2_w, m2f2_b, p_res+OFF, p_res+OFF, BNTOT, HIDDEN, DIMC);
    transpose_out_kernel<<<dim3(32,12,16), lnb>>>(p_res+OFF, outp + OFF);
}

// round 3
// speedup vs baseline: 3.0704x; 1.9137x over previous
#include <cuda_runtime.h>
#include <cuda_bf16.h>
#include <math.h>
#include <stdint.h>

#define DIMC 384
#define NSEQ 1024
#define BATCH 16
#define BNTOT (BATCH*NSEQ)
#define NHEAD 6
#define HD 64
#define HIDDEN 1536
#define SCALE 0.125f
#define EPSV 1e-5f

/* ------------------------------------------------------------------ */
/* scratch                                                             */
/* ------------------------------------------------------------------ */
__device__ float g_emb [2][BNTOT*DIMC];
__device__ float g_xn  [2][BNTOT*DIMC];
__device__ float g_kqv [2][BNTOT*3*DIMC];
__device__ float g_attn[2][BNTOT*DIMC];
__device__ float g_res [2][BNTOT*DIMC];
__device__ float g_h   [BNTOT*DIMC];
__device__ float g_gbuf[BNTOT*HIDDEN];

/* ------------------------------------------------------------------ */
/* shared PTX helpers                                                  */
/* ------------------------------------------------------------------ */
__device__ __forceinline__ uint32_t smem_u32(const void* p) {
    return (uint32_t)__cvta_generic_to_shared(p);
}
__device__ __forceinline__ void ldm_x4(uint32_t* r, uint32_t addr) {
    asm volatile("ldmatrix.sync.aligned.m8n8.x4.shared.b16 {%0,%1,%2,%3}, [%4];"
        : "=r"(r[0]), "=r"(r[1]), "=r"(r[2]), "=r"(r[3]) : "r"(addr));
}
__device__ __forceinline__ void ldm_x4_t(uint32_t* r, uint32_t addr) {
    asm volatile("ldmatrix.sync.aligned.m8n8.x4.trans.shared.b16 {%0,%1,%2,%3}, [%4];"
        : "=r"(r[0]), "=r"(r[1]), "=r"(r[2]), "=r"(r[3]) : "r"(addr));
}
__device__ __forceinline__ void mma_bf16(float* d, const uint32_t* a, const uint32_t* b) {
    asm volatile(
        "mma.sync.aligned.m16n8k16.row.col.f32.bf16.bf16.f32 "
        "{%0,%1,%2,%3}, {%4,%5,%6,%7}, {%8,%9}, {%0,%1,%2,%3};"
        : "+f"(d[0]), "+f"(d[1]), "+f"(d[2]), "+f"(d[3])
        : "r"(a[0]), "r"(a[1]), "r"(a[2]), "r"(a[3]), "r"(b[0]), "r"(b[1]));
}
__device__ __forceinline__ uint32_t pack_bf16(float x, float y) {
    __nv_bfloat162 t = __float22bfloat162_rn({x, y});
    return *(uint32_t*)&t;
}

/* ------------------------------------------------------------------ */
/* K1: LayerNorm over channel dim + transpose [B,C,N] -> [B,N,C]      */
/* ------------------------------------------------------------------ */
#define LN_SMEM ((384*33 + 32 + 32 + 8*32*2) * 4)
__global__ void __launch_bounds__(256) ln_transpose_kernel(
    const float* __restrict__ x, const float* __restrict__ w,
    const float* __restrict__ bvec,
    float* __restrict__ emb, float* __restrict__ xn)
{
    extern __shared__ float sm[];
    float* tile  = sm;
    float* meanv = tile + 384*33;
    float* rstdv = meanv + 32;
    float* ps    = rstdv + 32;
    float* pq    = ps + 8*32;

    const int n0 = blockIdx.x * 32;
    const int b  = blockIdx.y;
    const int tx = threadIdx.x, ty = threadIdx.y;

    float s = 0.f, q = 0.f;
    for (int c = ty; c < DIMC; c += 8) {
        float v = x[(b*DIMC + c)*NSEQ + n0 + tx];
        tile[c*33 + tx] = v;
        s += v; q += v*v;
    }
    ps[ty*32+tx] = s; pq[ty*32+tx] = q;
    __syncthreads();
    if (ty == 0) {
        float S = 0.f, Q = 0.f;
        #pragma unroll
        for (int j = 0; j < 8; ++j) { S += ps[j*32+tx]; Q += pq[j*32+tx]; }
        float mu = S * (1.f/DIMC);
        meanv[tx] = mu;
        rstdv[tx] = rsqrtf(Q*(1.f/DIMC) - mu*mu + EPSV);
    }
    __syncthreads();
    const int tid  = ty*32 + tx;
    const int base = (b*NSEQ + n0)*DIMC;
    for (int idx = tid; idx < 32*DIMC; idx += 256) {
        int nl = idx / DIMC, c = idx - nl*DIMC;
        float v = tile[c*33 + nl];
        emb[base + idx] = v;
        xn [base + idx] = (v - meanv[nl]) * rstdv[nl] * w[c] + bvec[c];
    }
}

/* ------------------------------------------------------------------ */
/* K2: bf16 tensor-core GEMM (unchanged from R2)                      */
/* ------------------------------------------------------------------ */
__device__ __forceinline__ float gelu_f(float x) {
    return 0.5f * x * (1.f + erff(x * 0.7071067811865475f));
}

#define ALD 40
#define BLD 136

template<int EPI>
__global__ void __launch_bounds__(256) hgemm_kernel(
    const float* __restrict__ A, const float* __restrict__ B,
    const float* __restrict__ bias, const float* __restrict__ res,
    float* __restrict__ C, int M, int K, int N)
{
    __shared__ __nv_bfloat16 As[2][128*ALD];
    __shared__ __nv_bfloat16 Bs[2][32*BLD];

    const int bm = blockIdx.y * 128, bn = blockIdx.x * 128;
    const int tid  = threadIdx.x;
    const int lane = tid & 31, wid = tid >> 5;
    const int wm = wid & 1, wn = wid >> 1;

    const int arow = tid >> 1, acol = (tid & 1) * 16;
    const int brow = tid >> 3, bcol = (tid & 7) * 16;
    const float* Ag = A + (size_t)(bm + arow)*K + acol;
    const float* Bg = B + (size_t)brow*N + bn + bcol;

    float4 ar[4], br[4];
    const int nch = K >> 5;

    #pragma unroll
    for (int i = 0; i < 4; ++i) ar[i] = *(const float4*)(Ag + i*4);
    #pragma unroll
    for (int i = 0; i < 4; ++i) br[i] = *(const float4*)(Bg + i*4);

    auto store_smem = [&](int buf) {
        __nv_bfloat16* ap = &As[buf][arow*ALD + acol];
        __nv_bfloat16* bp = &Bs[buf][brow*BLD + bcol];
        #pragma unroll
        for (int i = 0; i < 4; ++i) {
            *(__nv_bfloat162*)(ap + i*4    ) = __float22bfloat162_rn({ar[i].x, ar[i].y});
            *(__nv_bfloat162*)(ap + i*4 + 2) = __float22bfloat162_rn({ar[i].z, ar[i].w});
            *(__nv_bfloat162*)(bp + i*4    ) = __float22bfloat162_rn({br[i].x, br[i].y});
            *(__nv_bfloat162*)(bp + i*4 + 2) = __float22bfloat162_rn({br[i].z, br[i].w});
        }
    };
    store_smem(0);
    __syncthreads();

    float acc[4][4][4];
    #pragma unroll
    for (int i=0;i<4;++i)
        #pragma unroll
        for (int j=0;j<4;++j)
            #pragma unroll
            for (int u=0;u<4;++u) acc[i][j][u]=0.f;

    const int a_r = (lane & 15), a_c8 = (lane >> 4) * 8;
    const int b_k = (lane & 15), b_n8 = (lane >> 4) * 8;

    for (int c = 0; c < nch; ++c) {
        const int buf = c & 1;
        if (c + 1 < nch) {
            const float* Agn = Ag + (c+1)*32;
            const float* Bgn = Bg + (size_t)(c+1)*32*N;
            #pragma unroll
            for (int i = 0; i < 4; ++i) ar[i] = *(const float4*)(Agn + i*4);
            #pragma unroll
            for (int i = 0; i < 4; ++i) br[i] = *(const float4*)(Bgn + i*4);
        }

        #pragma unroll
        for (int ks = 0; ks < 2; ++ks) {
            uint32_t af[4][4], bf[4][2];
            #pragma unroll
            for (int mt = 0; mt < 4; ++mt) {
                int row = wm*64 + mt*16 + a_r;
                int col = ks*16 + a_c8;
                ldm_x4(af[mt], smem_u32(&As[buf][row*ALD + col]));
            }
            #pragma unroll
            for (int np = 0; np < 2; ++np) {
                uint32_t rr[4];
                int kk = ks*16 + b_k;
                int nn = wn*32 + np*16 + b_n8;
                ldm_x4_t(rr, smem_u32(&Bs[buf][kk*BLD + nn]));
                bf[np*2  ][0]=rr[0]; bf[np*2  ][1]=rr[1];
                bf[np*2+1][0]=rr[2]; bf[np*2+1][1]=rr[3];
            }
            #pragma unroll
            for (int mt = 0; mt < 4; ++mt)
                #pragma unroll
                for (int nt = 0; nt < 4; ++nt)
                    mma_bf16(acc[mt][nt], af[mt], bf[nt]);
        }
        __syncthreads();
        if (c + 1 < nch) {
            store_smem((c+1) & 1);
            __syncthreads();
        }
    }

    const int g = lane >> 2, qp = lane & 3;
    #pragma unroll
    for (int mt = 0; mt < 4; ++mt) {
        #pragma unroll
        for (int half = 0; half < 2; ++half) {
            int r = bm + wm*64 + mt*16 + g + half*8;
            #pragma unroll
            for (int nt = 0; nt < 4; ++nt) {
                int cix = bn + wn*32 + nt*8 + qp*2;
                float v0 = acc[mt][nt][half*2+0];
                float v1 = acc[mt][nt][half*2+1];
                if (EPI >= 1) { v0 += bias[cix]; v1 += bias[cix+1]; }
                if (EPI == 2) { v0 = gelu_f(v0); v1 = gelu_f(v1); }
                if (EPI == 1) {
                    float2 rr = *(const float2*)(res + (size_t)r*N + cix);
                    v0 += rr.x; v1 += rr.y;
                }
                float2 o = {v0, v1};
                *(float2*)(C + (size_t)r*N + cix) = o;
            }
        }
    }
}

/* ------------------------------------------------------------------ */
/* K3: bf16 tensor-core flash attention                               */
/* 128 thr = 4 warps; each warp owns a 16-row q band; Br=Bc=64, d=64  */
/* ------------------------------------------------------------------ */
#define QPAD 72   /* bf16 row stride: 144B -> rows offset 4 banks, conflict-free */

__global__ void __launch_bounds__(128) attn_bf16_kernel(
    const float* __restrict__ kqvQ, const float* __restrict__ kqvKV,
    float* __restrict__ outp)
{
    __shared__ __nv_bfloat16 Qs [64*QPAD];   /* [qrow][dim]  */
    __shared__ __nv_bfloat16 Kts[64*QPAD];   /* [dim][key]   */
    __shared__ __nv_bfloat16 Vs [64*QPAD];   /* [key][dim]   */

    const int qt = blockIdx.x, h = blockIdx.y, b = blockIdx.z;
    const int tid = threadIdx.x, lane = tid & 31, w = tid >> 5;

    const float* qb = kqvQ  + (size_t)(b*NSEQ + qt*64)*1152 + DIMC + h*HD;
    const float* kb = kqvKV + (size_t)(b*NSEQ)*1152                + h*HD;
    const float* vb = kqvKV + (size_t)(b*NSEQ)*1152 + 2*DIMC       + h*HD;

    /* load Q tile (pre-scaled) */
    for (int idx = tid; idx < 64*16; idx += 128) {
        int r = idx >> 4, f = (idx & 15) << 2;
        float4 v = *(const float4*)(qb + (size_t)r*1152 + f);
        __nv_bfloat16* p = &Qs[r*QPAD + f];
        *(__nv_bfloat162*)(p  ) = __float22bfloat162_rn({v.x*SCALE, v.y*SCALE});
        *(__nv_bfloat162*)(p+2) = __float22bfloat162_rn({v.z*SCALE, v.w*SCALE});
    }
    __syncthreads();

    /* Q A-fragments: constant for all KV tiles — hoisted */
    const int a_r = (lane & 15), a_c8 = (lane >> 4) * 8;
    uint32_t qa[4][4];
    #pragma unroll
    for (int ks = 0; ks < 4; ++ks)
        ldm_x4(qa[ks], smem_u32(&Qs[(w*16 + a_r)*QPAD + ks*16 + a_c8]));

    float m0 = -1e30f, m1 = -1e30f, l0 = 0.f, l1 = 0.f;
    float oacc[8][4];
    #pragma unroll
    for (int i=0;i<8;++i)
        #pragma unroll
        for (int u=0;u<4;++u) oacc[i][u]=0.f;

    for (int t = 0; t < 16; ++t) {
        __syncthreads();   /* prior iter's Kts/Vs reads done */
        for (int idx = tid; idx < 64*16; idx += 128) {
            int r = idx >> 4, f = (idx & 15) << 2;
            float4 kv = *(const float4*)(kb + (size_t)(t*64 + r)*1152 + f);
            Kts[(f+0)*QPAD + r] = __float2bfloat16(kv.x);
            Kts[(f+1)*QPAD + r] = __float2bfloat16(kv.y);
            Kts[(f+2)*QPAD + r] = __float2bfloat16(kv.z);
            Kts[(f+3)*QPAD + r] = __float2bfloat16(kv.w);
            float4 vv = *(const float4*)(vb + (size_t)(t*64 + r)*1152 + f);
            __nv_bfloat16* p = &Vs[r*QPAD + f];
            *(__nv_bfloat162*)(p  ) = __float22bfloat162_rn({vv.x, vv.y});
            *(__nv_bfloat162*)(p+2) = __float22bfloat162_rn({vv.z, vv.w});
        }
        __syncthreads();

        /* S = Q @ K^T : warp computes 16x64 */
        float sacc[8][4];
        #pragma unroll
        for (int i=0;i<8;++i)
            #pragma unroll
            for (int u=0;u<4;++u) sacc[i][u]=0.f;
        #pragma unroll
        for (int ks = 0; ks < 4; ++ks) {
            #pragma unroll
            for (int grp = 0; grp < 4; ++grp) {
                uint32_t kf[4];
                ldm_x4_t(kf, smem_u32(&Kts[(ks*16 + a_r)*QPAD + grp*16 + a_c8]));
                mma_bf16(sacc[grp*2  ], qa[ks], kf    );
                mma_bf16(sacc[grp*2+1], qa[ks], kf + 2);
            }
        }

        /* online softmax, rows g and g+8; quad reduction via shfl */
        float rmax0 = -1e30f, rmax1 = -1e30f;
        #pragma unroll
        for (int nt = 0; nt < 8; ++nt) {
            rmax0 = fmaxf(rmax0, fmaxf(sacc[nt][0], sacc[nt][1]));
            rmax1 = fmaxf(rmax1, fmaxf(sacc[nt][2], sacc[nt][3]));
        }
        rmax0 = fmaxf(rmax0, __shfl_xor_sync(0xffffffffu, rmax0, 1));
        rmax0 = fmaxf(rmax0, __shfl_xor_sync(0xffffffffu, rmax0, 2));
        rmax1 = fmaxf(rmax1, __shfl_xor_sync(0xffffffffu, rmax1, 1));
        rmax1 = fmaxf(rmax1, __shfl_xor_sync(0xffffffffu, rmax1, 2));

        float mnew0 = fmaxf(m0, rmax0), mnew1 = fmaxf(m1, rmax1);
        float alpha0 = __expf(m0 - mnew0), alpha1 = __expf(m1 - mnew1);
        m0 = mnew0; m1 = mnew1;

        float rsum0 = 0.f, rsum1 = 0.f;
        #pragma unroll
        for (int nt = 0; nt < 8; ++nt) {
            sacc[nt][0] = __expf(sacc[nt][0] - mnew0);
            sacc[nt][1] = __expf(sacc[nt][1] - mnew0);
            sacc[nt][2] = __expf(sacc[nt][2] - mnew1);
            sacc[nt][3] = __expf(sacc[nt][3] - mnew1);
            rsum0 += sacc[nt][0] + sacc[nt][1];
            rsum1 += sacc[nt][2] + sacc[nt][3];
        }
        rsum0 += __shfl_xor_sync(0xffffffffu, rsum0, 1);
        rsum0 += __shfl_xor_sync(0xffffffffu, rsum0, 2);
        rsum1 += __shfl_xor_sync(0xffffffffu, rsum1, 1);
        rsum1 += __shfl_xor_sync(0xffffffffu, rsum1, 2);
        l0 = l0*alpha0 + rsum0;
        l1 = l1*alpha1 + rsum1;

        #pragma unroll
        for (int i=0;i<8;++i) {
            oacc[i][0] *= alpha0; oacc[i][1] *= alpha0;
            oacc[i][2] *= alpha1; oacc[i][3] *= alpha1;
        }

        /* O += P @ V : P fragments come straight from sacc registers */
        #pragma unroll
        for (int ks = 0; ks < 4; ++ks) {
            uint32_t pa[4];
            pa[0] = pack_bf16(sacc[2*ks  ][0], sacc[2*ks  ][1]);
            pa[1] = pack_bf16(sacc[2*ks  ][2], sacc[2*ks  ][3]);
            pa[2] = pack_bf16(sacc[2*ks+1][0], sacc[2*ks+1][1]);
            pa[3] = pack_bf16(sacc[2*ks+1][2], sacc[2*ks+1][3]);
            #pragma unroll
            for (int dg = 0; dg < 4; ++dg) {
                uint32_t vf[4];
                ldm_x4_t(vf, smem_u32(&Vs[(ks*16 + a_r)*QPAD + dg*16 + a_c8]));
                mma_bf16(oacc[dg*2  ], pa, vf    );
                mma_bf16(oacc[dg*2+1], pa, vf + 2);
            }
        }
    }

    /* epilogue */
    const float inv0 = 1.f / l0, inv1 = 1.f / l1;
    const int g = lane >> 2, qp = lane & 3;
    const size_t r0 = (size_t)(b*NSEQ + qt*64 + w*16 + g)*DIMC + h*HD;
    #pragma unroll
    for (int nt = 0; nt < 8; ++nt) {
        int col = nt*8 + qp*2;
        float2 o0 = {oacc[nt][0]*inv0, oacc[nt][1]*inv0};
        float2 o1 = {oacc[nt][2]*inv1, oacc[nt][3]*inv1};
        *(float2*)(outp + r0 + col)            = o0;
        *(float2*)(outp + r0 + 8*DIMC + col)   = o1;
    }
}

/* ------------------------------------------------------------------ */
/* K4: row LayerNorm over last dim 384                                */
/* ------------------------------------------------------------------ */
__global__ void __launch_bounds__(128) ln_rows_kernel(
    const float* __restrict__ in, const float* __restrict__ w,
    const float* __restrict__ bb, float* __restrict__ out)
{
    const int row = blockIdx.x;
    const float* p = in + (size_t)row*DIMC;
    const int tid = threadIdx.x;
    float v0 = p[tid], v1 = p[tid+128], v2 = p[tid+256];
    float s = v0+v1+v2;
    float q = v0*v0 + v1*v1 + v2*v2;
    #pragma unroll
    for (int o = 16; o; o >>= 1) {
        s += __shfl_xor_sync(0xffffffffu, s, o);
        q += __shfl_xor_sync(0xffffffffu, q, o);
    }
    __shared__ float ss[4], qq[4];
    if ((tid & 31) == 0) { ss[tid>>5] = s; qq[tid>>5] = q; }
    __syncthreads();
    s = ss[0]+ss[1]+ss[2]+ss[3];
    q = qq[0]+qq[1]+qq[2]+qq[3];
    float mu = s * (1.f/DIMC);
    float rs = rsqrtf(q*(1.f/DIMC) - mu*mu + EPSV);
    out[(size_t)row*DIMC + tid      ] = (v0-mu)*rs*w[tid      ] + bb[tid      ];
    out[(size_t)row*DIMC + tid + 128] = (v1-mu)*rs*w[tid + 128] + bb[tid + 128];
    out[(size_t)row*DIMC + tid + 256] = (v2-mu)*rs*w[tid + 256] + bb[tid + 256];
}

/* ------------------------------------------------------------------ */
/* K5: transpose [B,N,C] -> [B,C,N] into d_out                        */
/* ------------------------------------------------------------------ */
__global__ void __launch_bounds__(256) transpose_out_kernel(
    const float* __restrict__ in, float* __restrict__ outp)
{
    __shared__ float t[32][33];
    const int n0 = blockIdx.x*32, c0 = blockIdx.y*32, b = blockIdx.z;
    const int tx = threadIdx.x, ty = threadIdx.y;
    #pragma unroll
    for (int i = ty; i < 32; i += 8)
        t[i][tx] = in[(size_t)(b*NSEQ + n0+i)*DIMC + c0 + tx];
    __syncthreads();
    #pragma unroll
    for (int i = ty; i < 32; i += 8)
        outp[(size_t)(b*DIMC + c0+i)*NSEQ + n0 + tx] = t[tx][i];
}

/* ------------------------------------------------------------------ */
extern "C" void kernel_launch(void* const* d_in, const int* in_sizes, int n_in,
                              void* d_out, int out_size)
{
    (void)in_sizes; (void)n_in; (void)out_size;
    const float* x1       = (const float*)d_in[0];
    const float* x2       = (const float*)d_in[1];
    const float* ln_a1_w  = (const float*)d_in[2];
    const float* ln_a1_b  = (const float*)d_in[3];
    const float* kqv1_w   = (const float*)d_in[4];
    const float* ln_a2_w  = (const float*)d_in[5];
    const float* ln_a2_b  = (const float*)d_in[6];
    const float* kqv2_w   = (const float*)d_in[7];
    const float* proj1_w  = (const float*)d_in[8];
    const float* proj1_b  = (const float*)d_in[9];
    const float* proj2_w  = (const float*)d_in[10];
    const float* proj2_b  = (const float*)d_in[11];
    const float* ln1_w    = (const float*)d_in[12];
    const float* ln1_b    = (const float*)d_in[13];
    const float* ln2_w    = (const float*)d_in[14];
    const float* ln2_b    = (const float*)d_in[15];
    const float* m1f1_w   = (const float*)d_in[16];
    const float* m1f1_b   = (const float*)d_in[17];
    const float* m1f2_w   = (const float*)d_in[18];
    const float* m1f2_b   = (const float*)d_in[19];
    const float* m2f1_w   = (const float*)d_in[20];
    const float* m2f1_b   = (const float*)d_in[21];
    const float* m2f2_w   = (const float*)d_in[22];
    const float* m2f2_b   = (const float*)d_in[23];
    float* outp = (float*)d_out;

    float *p_emb, *p_xn, *p_kqv, *p_attn, *p_res, *p_h, *p_g;
    cudaGetSymbolAddress((void**)&p_emb,  g_emb);
    cudaGetSymbolAddress((void**)&p_xn,   g_xn);
    cudaGetSymbolAddress((void**)&p_kqv,  g_kqv);
    cudaGetSymbolAddress((void**)&p_attn, g_attn);
    cudaGetSymbolAddress((void**)&p_res,  g_res);
    cudaGetSymbolAddress((void**)&p_h,    g_h);
    cudaGetSymbolAddress((void**)&p_g,    g_gbuf);

    cudaFuncSetAttribute(ln_transpose_kernel,
        cudaFuncAttributeMaxDynamicSharedMemorySize, LN_SMEM);

    const int OFF  = BNTOT*DIMC;
    const int KOFF = BNTOT*3*DIMC;
    const dim3 lnb(32, 8);

    ln_transpose_kernel<<<dim3(32,16), lnb, LN_SMEM>>>(x1, ln_a1_w, ln_a1_b, p_emb,     p_xn);
    ln_transpose_kernel<<<dim3(32,16), lnb, LN_SMEM>>>(x2, ln_a2_w, ln_a2_b, p_emb+OFF, p_xn+OFF);

    hgemm_kernel<0><<<dim3(9,128),  256>>>(p_xn,     kqv1_w, nullptr, nullptr, p_kqv,      BNTOT, DIMC, 3*DIMC);
    hgemm_kernel<0><<<dim3(9,128),  256>>>(p_xn+OFF, kqv2_w, nullptr, nullptr, p_kqv+KOFF, BNTOT, DIMC, 3*DIMC);

    attn_bf16_kernel<<<dim3(16,6,16), 128>>>(p_kqv,      p_kqv+KOFF, p_attn);
    attn_bf16_kernel<<<dim3(16,6,16), 128>>>(p_kqv+KOFF, p_kqv,      p_attn+OFF);

    hgemm_kernel<1><<<dim3(3,128),  256>>>(p_attn, proj1_w, proj1_b, p_emb, p_res, BNTOT, DIMC, DIMC);
    ln_rows_kernel<<<BNTOT, 128>>>(p_res, ln1_w, ln1_b, p_h);
    hgemm_kernel<2><<<dim3(12,128), 256>>>(p_h, m1f1_w, m1f1_b, nullptr, p_g, BNTOT, DIMC, HIDDEN);
    hgemm_kernel<1><<<dim3(3,128),  256>>>(p_g, m1f2_w, m1f2_b, p_res, p_res, BNTOT, HIDDEN, DIMC);
    transpose_out_kernel<<<dim3(32,12,16), lnb>>>(p_res, outp);

    hgemm_kernel<1><<<dim3(3,128),  256>>>(p_attn+OFF, proj2_w, proj2_b, p_emb+OFF, p_res+OFF, BNTOT, DIMC, DIMC);
    ln_rows_kernel<<<BNTOT, 128>>>(p_res+OFF, ln2_w, ln2_b, p_h);
    hgemm_kernel<2><<<dim3(12,128), 256>>>(p_h, m2f1_w, m2f1_b, nullptr, p_g, BNTOT, DIMC, HIDDEN);
    hgemm_kernel<1><<<dim3(3,128),  256>>>(p_g, m2f2_w, m2f2_b, p_res+OFF, p_res+OFF, BNTOT, HIDDEN, DIMC);
    transpose_out_kernel<<<dim3(32,12,16), lnb>>>(p_res+OFF, outp + OFF);
}

// round 4
// speedup vs baseline: 4.5102x; 1.4689x over previous
#include <cuda_runtime.h>
#include <cuda_bf16.h>
#include <math.h>
#include <stdint.h>

#define DIMC 384
#define NSEQ 1024
#define BATCH 16
#define BNTOT (BATCH*NSEQ)
#define NHEAD 6
#define HD 64
#define HIDDEN 1536
#define SCALE 0.125f
#define EPSV 1e-5f

typedef __nv_bfloat16 bf16;

/* ------------------------------------------------------------------ */
/* scratch                                                             */
/* ------------------------------------------------------------------ */
__device__ float g_emb [2][BNTOT*DIMC];
__device__ bf16  g_xn  [2][BNTOT*DIMC];
__device__ bf16  g_kqv [2][BNTOT*3*DIMC];
__device__ bf16  g_attn[2][BNTOT*DIMC];
__device__ float g_res [2][BNTOT*DIMC];
__device__ bf16  g_h   [BNTOT*DIMC];
__device__ bf16  g_gbuf[BNTOT*HIDDEN];

#define W_KQV   (DIMC*3*DIMC)      /* 442368 */
#define W_PROJ  (DIMC*DIMC)        /* 147456 */
#define W_FC    (DIMC*HIDDEN)      /* 589824 */
__device__ bf16 g_wbf[2*W_KQV + 2*W_PROJ + 4*W_FC];

/* ------------------------------------------------------------------ */
/* PTX helpers                                                         */
/* ------------------------------------------------------------------ */
__device__ __forceinline__ uint32_t smem_u32(const void* p) {
    return (uint32_t)__cvta_generic_to_shared(p);
}
__device__ __forceinline__ void ldm_x4(uint32_t* r, uint32_t addr) {
    asm volatile("ldmatrix.sync.aligned.m8n8.x4.shared.b16 {%0,%1,%2,%3}, [%4];"
        : "=r"(r[0]), "=r"(r[1]), "=r"(r[2]), "=r"(r[3]) : "r"(addr));
}
__device__ __forceinline__ void ldm_x4_t(uint32_t* r, uint32_t addr) {
    asm volatile("ldmatrix.sync.aligned.m8n8.x4.trans.shared.b16 {%0,%1,%2,%3}, [%4];"
        : "=r"(r[0]), "=r"(r[1]), "=r"(r[2]), "=r"(r[3]) : "r"(addr));
}
__device__ __forceinline__ void mma_bf16(float* d, const uint32_t* a, const uint32_t* b) {
    asm volatile(
        "mma.sync.aligned.m16n8k16.row.col.f32.bf16.bf16.f32 "
        "{%0,%1,%2,%3}, {%4,%5,%6,%7}, {%8,%9}, {%0,%1,%2,%3};"
        : "+f"(d[0]), "+f"(d[1]), "+f"(d[2]), "+f"(d[3])
        : "r"(a[0]), "r"(a[1]), "r"(a[2]), "r"(a[3]), "r"(b[0]), "r"(b[1]));
}
__device__ __forceinline__ uint32_t pack_bf16(float x, float y) {
    __nv_bfloat162 t = __float22bfloat162_rn({x, y});
    return *(uint32_t*)&t;
}
__device__ __forceinline__ void cp16(uint32_t dst, const void* src) {
    asm volatile("cp.async.cg.shared.global [%0], [%1], 16;" :: "r"(dst), "l"(src));
}
#define CP_COMMIT() asm volatile("cp.async.commit_group;")
#define CP_WAIT(n)  asm volatile("cp.async.wait_group %0;" :: "n"(n))

/* ------------------------------------------------------------------ */
/* K0: fp32 -> bf16 convert (weights)                                  */
/* ------------------------------------------------------------------ */
__global__ void __launch_bounds__(256) f2bf_kernel(
    const float* __restrict__ in, bf16* __restrict__ out, int n)
{
    int i = (blockIdx.x*blockDim.x + threadIdx.x)*4;
    if (i < n) {
        float4 v = *(const float4*)(in + i);
        *(__nv_bfloat162*)(out + i    ) = __float22bfloat162_rn({v.x, v.y});
        *(__nv_bfloat162*)(out + i + 2) = __float22bfloat162_rn({v.z, v.w});
    }
}

/* ------------------------------------------------------------------ */
/* K1: LayerNorm over channel dim + transpose [B,C,N] -> [B,N,C]      */
/* emb fp32, xn bf16                                                   */
/* ------------------------------------------------------------------ */
#define LN_SMEM ((384*33 + 32 + 32 + 8*32*2) * 4)
__global__ void __launch_bounds__(256) ln_transpose_kernel(
    const float* __restrict__ x, const float* __restrict__ w,
    const float* __restrict__ bvec,
    float* __restrict__ emb, bf16* __restrict__ xn)
{
    extern __shared__ float sm[];
    float* tile  = sm;
    float* meanv = tile + 384*33;
    float* rstdv = meanv + 32;
    float* ps    = rstdv + 32;
    float* pq    = ps + 8*32;

    const int n0 = blockIdx.x * 32;
    const int b  = blockIdx.y;
    const int tx = threadIdx.x, ty = threadIdx.y;

    float s = 0.f, q = 0.f;
    for (int c = ty; c < DIMC; c += 8) {
        float v = x[(b*DIMC + c)*NSEQ + n0 + tx];
        tile[c*33 + tx] = v;
        s += v; q += v*v;
    }
    ps[ty*32+tx] = s; pq[ty*32+tx] = q;
    __syncthreads();
    if (ty == 0) {
        float S = 0.f, Q = 0.f;
        #pragma unroll
        for (int j = 0; j < 8; ++j) { S += ps[j*32+tx]; Q += pq[j*32+tx]; }
        float mu = S * (1.f/DIMC);
        meanv[tx] = mu;
        rstdv[tx] = rsqrtf(Q*(1.f/DIMC) - mu*mu + EPSV);
    }
    __syncthreads();
    const int tid  = ty*32 + tx;
    const int base = (b*NSEQ + n0)*DIMC;
    for (int idx = tid; idx < 32*DIMC; idx += 256) {
        int nl = idx / DIMC, c = idx - nl*DIMC;
        float v = tile[c*33 + nl];
        emb[base + idx] = v;
        xn [base + idx] = __float2bfloat16((v - meanv[nl]) * rstdv[nl] * w[c] + bvec[c]);
    }
}

/* ------------------------------------------------------------------ */
/* K2: bf16 GEMM, cp.async 2-stage, 128x128x32, mma m16n8k16          */
/* EPI: 0 plain, 1 +bias+residual(fp32), 2 +bias+GELU                 */
/* OUTBF: write bf16 instead of fp32                                   */
/* ------------------------------------------------------------------ */
__device__ __forceinline__ float gelu_f(float x) {
    return 0.5f * x * (1.f + erff(x * 0.7071067811865475f));
}

#define ALD 40
#define BLD 136

template<int EPI, bool OUTBF>
__global__ void __launch_bounds__(256) hgemm2_kernel(
    const bf16* __restrict__ A, const bf16* __restrict__ B,
    const float* __restrict__ bias, const float* __restrict__ res,
    void* __restrict__ Cout, int M, int K, int N)
{
    __shared__ bf16 As[2][128*ALD];
    __shared__ bf16 Bs[2][32*BLD];

    const int bm = blockIdx.y * 128, bn = blockIdx.x * 128;
    const int tid  = threadIdx.x;
    const int lane = tid & 31, wid = tid >> 5;
    const int wm = wid & 1, wn = wid >> 1;

    /* cp.async mappings: A 128x32 (2x16B/thr), B 32x128 (2x16B/thr) */
    const int arow = tid >> 1, acol = (tid & 1) * 16;
    const int brow = tid >> 3, bcol = (tid & 7) * 16;
    const bf16* Ag = A + (size_t)(bm + arow)*K + acol;
    const bf16* Bg = B + (size_t)brow*N + bn + bcol;

    const uint32_t asm0 = smem_u32(&As[0][arow*ALD + acol]);
    const uint32_t asm1 = smem_u32(&As[1][arow*ALD + acol]);
    const uint32_t bsm0 = smem_u32(&Bs[0][brow*BLD + bcol]);
    const uint32_t bsm1 = smem_u32(&Bs[1][brow*BLD + bcol]);

    const int nch = K >> 5;

    auto issue = [&](int c) {
        uint32_t ad = (c & 1) ? asm1 : asm0;
        uint32_t bd = (c & 1) ? bsm1 : bsm0;
        const bf16* ag = Ag + c*32;
        const bf16* bg = Bg + (size_t)c*32*N;
        cp16(ad,      ag);
        cp16(ad + 16, ag + 8);
        cp16(bd,      bg);
        cp16(bd + 16, bg + 8);
    };

    issue(0);
    CP_COMMIT();

    float acc[4][4][4];
    #pragma unroll
    for (int i=0;i<4;++i)
        #pragma unroll
        for (int j=0;j<4;++j)
            #pragma unroll
            for (int u=0;u<4;++u) acc[i][j][u]=0.f;

    const int a_r = (lane & 15), a_c8 = (lane >> 4) * 8;
    const int b_k = (lane & 15), b_n8 = (lane >> 4) * 8;

    for (int c = 0; c < nch; ++c) {
        const int buf = c & 1;
        if (c + 1 < nch) {
            issue(c + 1);
            CP_COMMIT();
            CP_WAIT(1);
        } else {
            CP_WAIT(0);
        }
        __syncthreads();

        #pragma unroll
        for (int ks = 0; ks < 2; ++ks) {
            uint32_t af[4][4], bf[4][2];
            #pragma unroll
            for (int mt = 0; mt < 4; ++mt) {
                int row = wm*64 + mt*16 + a_r;
                int col = ks*16 + a_c8;
                ldm_x4(af[mt], smem_u32(&As[buf][row*ALD + col]));
            }
            #pragma unroll
            for (int np = 0; np < 2; ++np) {
                uint32_t rr[4];
                int kk = ks*16 + b_k;
                int nn = wn*32 + np*16 + b_n8;
                ldm_x4_t(rr, smem_u32(&Bs[buf][kk*BLD + nn]));
                bf[np*2  ][0]=rr[0]; bf[np*2  ][1]=rr[1];
                bf[np*2+1][0]=rr[2]; bf[np*2+1][1]=rr[3];
            }
            #pragma unroll
            for (int mt = 0; mt < 4; ++mt)
                #pragma unroll
                for (int nt = 0; nt < 4; ++nt)
                    mma_bf16(acc[mt][nt], af[mt], bf[nt]);
        }
        __syncthreads();
    }

    const int g = lane >> 2, qp = lane & 3;
    #pragma unroll
    for (int mt = 0; mt < 4; ++mt) {
        #pragma unroll
        for (int half = 0; half < 2; ++half) {
            int r = bm + wm*64 + mt*16 + g + half*8;
            #pragma unroll
            for (int nt = 0; nt < 4; ++nt) {
                int cix = bn + wn*32 + nt*8 + qp*2;
                float v0 = acc[mt][nt][half*2+0];
                float v1 = acc[mt][nt][half*2+1];
                if (EPI >= 1) { v0 += bias[cix]; v1 += bias[cix+1]; }
                if (EPI == 2) { v0 = gelu_f(v0); v1 = gelu_f(v1); }
                if (EPI == 1) {
                    float2 rr = *(const float2*)(res + (size_t)r*N + cix);
                    v0 += rr.x; v1 += rr.y;
                }
                if (OUTBF) {
                    bf16* Cb = (bf16*)Cout;
                    *(uint32_t*)(Cb + (size_t)r*N + cix) = pack_bf16(v0, v1);
                } else {
                    float* Cf = (float*)Cout;
                    float2 o = {v0, v1};
                    *(float2*)(Cf + (size_t)r*N + cix) = o;
                }
            }
        }
    }
}

/* ------------------------------------------------------------------ */
/* K3: bf16 flash attention, bf16 kqv input, bf16 output              */
/* 128 thr = 4 warps, warp = 16 q-rows; Br=Bc=64, d=64                */
/* K,V stored natural [key][dim]; S scaled post-mma                   */
/* ------------------------------------------------------------------ */
#define KPAD 72

__global__ void __launch_bounds__(128) attn2_kernel(
    const bf16* __restrict__ kqvQ, const bf16* __restrict__ kqvKV,
    bf16* __restrict__ outp)
{
    __shared__ bf16 Qs[64*KPAD];
    __shared__ bf16 Ks[64*KPAD];
    __shared__ bf16 Vs[64*KPAD];

    const int qt = blockIdx.x, h = blockIdx.y, b = blockIdx.z;
    const int tid = threadIdx.x, lane = tid & 31, w = tid >> 5;

    const bf16* qb = kqvQ  + (size_t)(b*NSEQ + qt*64)*1152 + DIMC + h*HD;
    const bf16* kb = kqvKV + (size_t)(b*NSEQ)*1152                + h*HD;
    const bf16* vb = kqvKV + (size_t)(b*NSEQ)*1152 + 2*DIMC       + h*HD;

    /* Q tile: 64 rows x 64 bf16 = 8 x 16B per row */
    for (int idx = tid; idx < 512; idx += 128) {
        int r = idx >> 3, s = (idx & 7) * 8;
        *(uint4*)&Qs[r*KPAD + s] = *(const uint4*)(qb + (size_t)r*1152 + s);
    }
    __syncthreads();

    const int a_r = (lane & 15), a_c8 = (lane >> 4) * 8;
    uint32_t qa[4][4];
    #pragma unroll
    for (int ks = 0; ks < 4; ++ks)
        ldm_x4(qa[ks], smem_u32(&Qs[(w*16 + a_r)*KPAD + ks*16 + a_c8]));

    float m0 = -1e30f, m1 = -1e30f, l0 = 0.f, l1 = 0.f;
    float oacc[8][4];
    #pragma unroll
    for (int i=0;i<8;++i)
        #pragma unroll
        for (int u=0;u<4;++u) oacc[i][u]=0.f;

    for (int t = 0; t < 16; ++t) {
        __syncthreads();
        for (int idx = tid; idx < 512; idx += 128) {
            int r = idx >> 3, s = (idx & 7) * 8;
            *(uint4*)&Ks[r*KPAD + s] = *(const uint4*)(kb + (size_t)(t*64 + r)*1152 + s);
            *(uint4*)&Vs[r*KPAD + s] = *(const uint4*)(vb + (size_t)(t*64 + r)*1152 + s);
        }
        __syncthreads();

        /* S = Q @ K^T : K natural [key][dim], non-trans ldmatrix,
           B-fragment pairs {r0,r2} (keys g*16..+7) and {r1,r3} (+8..15) */
        float sacc[8][4];
        #pragma unroll
        for (int i=0;i<8;++i)
            #pragma unroll
            for (int u=0;u<4;++u) sacc[i][u]=0.f;
        #pragma unroll
        for (int ks = 0; ks < 4; ++ks) {
            #pragma unroll
            for (int grp = 0; grp < 4; ++grp) {
                uint32_t kf[4];
                ldm_x4(kf, smem_u32(&Ks[(grp*16 + a_r)*KPAD + ks*16 + a_c8]));
                uint32_t b0[2] = {kf[0], kf[2]};
                uint32_t b1[2] = {kf[1], kf[3]};
                mma_bf16(sacc[grp*2  ], qa[ks], b0);
                mma_bf16(sacc[grp*2+1], qa[ks], b1);
            }
        }
        #pragma unroll
        for (int i=0;i<8;++i) {
            sacc[i][0]*=SCALE; sacc[i][1]*=SCALE;
            sacc[i][2]*=SCALE; sacc[i][3]*=SCALE;
        }

        /* online softmax */
        float rmax0 = -1e30f, rmax1 = -1e30f;
        #pragma unroll
        for (int nt = 0; nt < 8; ++nt) {
            rmax0 = fmaxf(rmax0, fmaxf(sacc[nt][0], sacc[nt][1]));
            rmax1 = fmaxf(rmax1, fmaxf(sacc[nt][2], sacc[nt][3]));
        }
        rmax0 = fmaxf(rmax0, __shfl_xor_sync(0xffffffffu, rmax0, 1));
        rmax0 = fmaxf(rmax0, __shfl_xor_sync(0xffffffffu, rmax0, 2));
        rmax1 = fmaxf(rmax1, __shfl_xor_sync(0xffffffffu, rmax1, 1));
        rmax1 = fmaxf(rmax1, __shfl_xor_sync(0xffffffffu, rmax1, 2));

        float mnew0 = fmaxf(m0, rmax0), mnew1 = fmaxf(m1, rmax1);
        float alpha0 = __expf(m0 - mnew0), alpha1 = __expf(m1 - mnew1);
        m0 = mnew0; m1 = mnew1;

        float rsum0 = 0.f, rsum1 = 0.f;
        #pragma unroll
        for (int nt = 0; nt < 8; ++nt) {
            sacc[nt][0] = __expf(sacc[nt][0] - mnew0);
            sacc[nt][1] = __expf(sacc[nt][1] - mnew0);
            sacc[nt][2] = __expf(sacc[nt][2] - mnew1);
            sacc[nt][3] = __expf(sacc[nt][3] - mnew1);
            rsum0 += sacc[nt][0] + sacc[nt][1];
            rsum1 += sacc[nt][2] + sacc[nt][3];
        }
        rsum0 += __shfl_xor_sync(0xffffffffu, rsum0, 1);
        rsum0 += __shfl_xor_sync(0xffffffffu, rsum0, 2);
        rsum1 += __shfl_xor_sync(0xffffffffu, rsum1, 1);
        rsum1 += __shfl_xor_sync(0xffffffffu, rsum1, 2);
        l0 = l0*alpha0 + rsum0;
        l1 = l1*alpha1 + rsum1;

        #pragma unroll
        for (int i=0;i<8;++i) {
            oacc[i][0] *= alpha0; oacc[i][1] *= alpha0;
            oacc[i][2] *= alpha1; oacc[i][3] *= alpha1;
        }

        /* O += P @ V : V natural [key][dim], trans ldmatrix (as R3) */
        #pragma unroll
        for (int ks = 0; ks < 4; ++ks) {
            uint32_t pa[4];
            pa[0] = pack_bf16(sacc[2*ks  ][0], sacc[2*ks  ][1]);
            pa[1] = pack_bf16(sacc[2*ks  ][2], sacc[2*ks  ][3]);
            pa[2] = pack_bf16(sacc[2*ks+1][0], sacc[2*ks+1][1]);
            pa[3] = pack_bf16(sacc[2*ks+1][2], sacc[2*ks+1][3]);
            #pragma unroll
            for (int dg = 0; dg < 4; ++dg) {
                uint32_t vf[4];
                ldm_x4_t(vf, smem_u32(&Vs[(ks*16 + a_r)*KPAD + dg*16 + a_c8]));
                mma_bf16(oacc[dg*2  ], pa, vf    );
                mma_bf16(oacc[dg*2+1], pa, vf + 2);
            }
        }
    }

    const float inv0 = 1.f / l0, inv1 = 1.f / l1;
    const int g = lane >> 2, qp = lane & 3;
    const size_t r0 = (size_t)(b*NSEQ + qt*64 + w*16 + g)*DIMC + h*HD;
    #pragma unroll
    for (int nt = 0; nt < 8; ++nt) {
        int col = nt*8 + qp*2;
        *(uint32_t*)(outp + r0 + col)          = pack_bf16(oacc[nt][0]*inv0, oacc[nt][1]*inv0);
        *(uint32_t*)(outp + r0 + 8*DIMC + col) = pack_bf16(oacc[nt][2]*inv1, oacc[nt][3]*inv1);
    }
}

/* ------------------------------------------------------------------ */
/* K4: row LayerNorm (fp32 in, bf16 out)                              */
/* ------------------------------------------------------------------ */
__global__ void __launch_bounds__(128) ln_rows_kernel(
    const float* __restrict__ in, const float* __restrict__ w,
    const float* __restrict__ bb, bf16* __restrict__ out)
{
    const int row = blockIdx.x;
    const float* p = in + (size_t)row*DIMC;
    const int tid = threadIdx.x;
    float v0 = p[tid], v1 = p[tid+128], v2 = p[tid+256];
    float s = v0+v1+v2;
    float q = v0*v0 + v1*v1 + v2*v2;
    #pragma unroll
    for (int o = 16; o; o >>= 1) {
        s += __shfl_xor_sync(0xffffffffu, s, o);
        q += __shfl_xor_sync(0xffffffffu, q, o);
    }
    __shared__ float ss[4], qq[4];
    if ((tid & 31) == 0) { ss[tid>>5] = s; qq[tid>>5] = q; }
    __syncthreads();
    s = ss[0]+ss[1]+ss[2]+ss[3];
    q = qq[0]+qq[1]+qq[2]+qq[3];
    float mu = s * (1.f/DIMC);
    float rs = rsqrtf(q*(1.f/DIMC) - mu*mu + EPSV);
    out[(size_t)row*DIMC + tid      ] = __float2bfloat16((v0-mu)*rs*w[tid      ] + bb[tid      ]);
    out[(size_t)row*DIMC + tid + 128] = __float2bfloat16((v1-mu)*rs*w[tid + 128] + bb[tid + 128]);
    out[(size_t)row*DIMC + tid + 256] = __float2bfloat16((v2-mu)*rs*w[tid + 256] + bb[tid + 256]);
}

/* ------------------------------------------------------------------ */
/* K5: transpose [B,N,C] -> [B,C,N] into d_out                        */
/* ------------------------------------------------------------------ */
__global__ void __launch_bounds__(256) transpose_out_kernel(
    const float* __restrict__ in, float* __restrict__ outp)
{
    __shared__ float t[32][33];
    const int n0 = blockIdx.x*32, c0 = blockIdx.y*32, b = blockIdx.z;
    const int tx = threadIdx.x, ty = threadIdx.y;
    #pragma unroll
    for (int i = ty; i < 32; i += 8)
        t[i][tx] = in[(size_t)(b*NSEQ + n0+i)*DIMC + c0 + tx];
    __syncthreads();
    #pragma unroll
    for (int i = ty; i < 32; i += 8)
        outp[(size_t)(b*DIMC + c0+i)*NSEQ + n0 + tx] = t[tx][i];
}

/* ------------------------------------------------------------------ */
extern "C" void kernel_launch(void* const* d_in, const int* in_sizes, int n_in,
                              void* d_out, int out_size)
{
    (void)in_sizes; (void)n_in; (void)out_size;
    const float* x1       = (const float*)d_in[0];
    const float* x2       = (const float*)d_in[1];
    const float* ln_a1_w  = (const float*)d_in[2];
    const float* ln_a1_b  = (const float*)d_in[3];
    const float* kqv1_w   = (const float*)d_in[4];
    const float* ln_a2_w  = (const float*)d_in[5];
    const float* ln_a2_b  = (const float*)d_in[6];
    const float* kqv2_w   = (const float*)d_in[7];
    const float* proj1_w  = (const float*)d_in[8];
    const float* proj1_b  = (const float*)d_in[9];
    const float* proj2_w  = (const float*)d_in[10];
    const float* proj2_b  = (const float*)d_in[11];
    const float* ln1_w    = (const float*)d_in[12];
    const float* ln1_b    = (const float*)d_in[13];
    const float* ln2_w    = (const float*)d_in[14];
    const float* ln2_b    = (const float*)d_in[15];
    const float* m1f1_w   = (const float*)d_in[16];
    const float* m1f1_b   = (const float*)d_in[17];
    const float* m1f2_w   = (const float*)d_in[18];
    const float* m1f2_b   = (const float*)d_in[19];
    const float* m2f1_w   = (const float*)d_in[20];
    const float* m2f1_b   = (const float*)d_in[21];
    const float* m2f2_w   = (const float*)d_in[22];
    const float* m2f2_b   = (const float*)d_in[23];
    float* outp = (float*)d_out;

    float *p_emb, *p_res;
    bf16 *p_xn, *p_kqv, *p_attn, *p_h, *p_g, *p_w;
    cudaGetSymbolAddress((void**)&p_emb,  g_emb);
    cudaGetSymbolAddress((void**)&p_xn,   g_xn);
    cudaGetSymbolAddress((void**)&p_kqv,  g_kqv);
    cudaGetSymbolAddress((void**)&p_attn, g_attn);
    cudaGetSymbolAddress((void**)&p_res,  g_res);
    cudaGetSymbolAddress((void**)&p_h,    g_h);
    cudaGetSymbolAddress((void**)&p_g,    g_gbuf);
    cudaGetSymbolAddress((void**)&p_w,    g_wbf);

    cudaFuncSetAttribute(ln_transpose_kernel,
        cudaFuncAttributeMaxDynamicSharedMemorySize, LN_SMEM);

    const int OFF  = BNTOT*DIMC;
    const int KOFF = BNTOT*3*DIMC;
    const dim3 lnb(32, 8);

    /* bf16 weight copies */
    bf16* w_kqv1 = p_w;
    bf16* w_kqv2 = w_kqv1 + W_KQV;
    bf16* w_pj1  = w_kqv2 + W_KQV;
    bf16* w_pj2  = w_pj1  + W_PROJ;
    bf16* w_f11  = w_pj2  + W_PROJ;
    bf16* w_f12  = w_f11  + W_FC;
    bf16* w_f21  = w_f12  + W_FC;
    bf16* w_f22  = w_f21  + W_FC;
    f2bf_kernel<<<(W_KQV/4+255)/256,  256>>>(kqv1_w,  w_kqv1, W_KQV);
    f2bf_kernel<<<(W_KQV/4+255)/256,  256>>>(kqv2_w,  w_kqv2, W_KQV);
    f2bf_kernel<<<(W_PROJ/4+255)/256, 256>>>(proj1_w, w_pj1,  W_PROJ);
    f2bf_kernel<<<(W_PROJ/4+255)/256, 256>>>(proj2_w, w_pj2,  W_PROJ);
    f2bf_kernel<<<(W_FC/4+255)/256,   256>>>(m1f1_w,  w_f11,  W_FC);
    f2bf_kernel<<<(W_FC/4+255)/256,   256>>>(m1f2_w,  w_f12,  W_FC);
    f2bf_kernel<<<(W_FC/4+255)/256,   256>>>(m2f1_w,  w_f21,  W_FC);
    f2bf_kernel<<<(W_FC/4+255)/256,   256>>>(m2f2_w,  w_f22,  W_FC);

    ln_transpose_kernel<<<dim3(32,16), lnb, LN_SMEM>>>(x1, ln_a1_w, ln_a1_b, p_emb,     p_xn);
    ln_transpose_kernel<<<dim3(32,16), lnb, LN_SMEM>>>(x2, ln_a2_w, ln_a2_b, p_emb+OFF, p_xn+OFF);

    hgemm2_kernel<0,true><<<dim3(9,128), 256>>>(p_xn,     w_kqv1, nullptr, nullptr, p_kqv,      BNTOT, DIMC, 3*DIMC);
    hgemm2_kernel<0,true><<<dim3(9,128), 256>>>(p_xn+OFF, w_kqv2, nullptr, nullptr, p_kqv+KOFF, BNTOT, DIMC, 3*DIMC);

    attn2_kernel<<<dim3(16,6,16), 128>>>(p_kqv,      p_kqv+KOFF, p_attn);
    attn2_kernel<<<dim3(16,6,16), 128>>>(p_kqv+KOFF, p_kqv,      p_attn+OFF);

    hgemm2_kernel<1,false><<<dim3(3,128),  256>>>(p_attn, w_pj1, proj1_b, p_emb, p_res, BNTOT, DIMC, DIMC);
    ln_rows_kernel<<<BNTOT, 128>>>(p_res, ln1_w, ln1_b, p_h);
    hgemm2_kernel<2,true ><<<dim3(12,128), 256>>>(p_h, w_f11, m1f1_b, nullptr, p_g, BNTOT, DIMC, HIDDEN);
    hgemm2_kernel<1,false><<<dim3(3,128),  256>>>(p_g, w_f12, m1f2_b, p_res, p_res, BNTOT, HIDDEN, DIMC);
    transpose_out_kernel<<<dim3(32,12,16), lnb>>>(p_res, outp);

    hgemm2_kernel<1,false><<<dim3(3,128),  256>>>(p_attn+OFF, w_pj2, proj2_b, p_emb+OFF, p_res+OFF, BNTOT, DIMC, DIMC);
    ln_rows_kernel<<<BNTOT, 128>>>(p_res+OFF, ln2_w, ln2_b, p_h);
    hgemm2_kernel<2,true ><<<dim3(12,128), 256>>>(p_h, w_f21, m2f1_b, nullptr, p_g, BNTOT, DIMC, HIDDEN);
    hgemm2_kernel<1,false><<<dim3(3,128),  256>>>(p_g, w_f22, m2f2_b, p_res+OFF, p_res+OFF, BNTOT, HIDDEN, DIMC);
    transpose_out_kernel<<<dim3(32,12,16), lnb>>>(p_res+OFF, outp + OFF);
}

// round 5
// speedup vs baseline: 5.1242x; 1.1361x over previous
#include <cuda_runtime.h>
#include <cuda_bf16.h>
#include <math.h>
#include <stdint.h>

#define DIMC 384
#define NSEQ 1024
#define BATCH 16
#define BNTOT (BATCH*NSEQ)
#define NHEAD 6
#define HD 64
#define HIDDEN 1536
#define EPSV 1e-5f

typedef __nv_bfloat16 bf16;

/* ------------------------------------------------------------------ */
/* scratch                                                             */
/* ------------------------------------------------------------------ */
__device__ float g_emb [2][BNTOT*DIMC];
__device__ bf16  g_xn  [2][BNTOT*DIMC];
__device__ bf16  g_kqv [2][BNTOT*3*DIMC];
__device__ bf16  g_attn[2][BNTOT*DIMC];
__device__ float g_res [2][BNTOT*DIMC];
__device__ bf16  g_h   [BNTOT*DIMC];
__device__ bf16  g_gbuf[BNTOT*HIDDEN];

#define W_KQV   (DIMC*3*DIMC)
#define W_PROJ  (DIMC*DIMC)
#define W_FC    (DIMC*HIDDEN)
__device__ bf16 g_wbf[2*W_KQV + 2*W_PROJ + 4*W_FC];

/* ------------------------------------------------------------------ */
/* PTX helpers                                                         */
/* ------------------------------------------------------------------ */
__device__ __forceinline__ uint32_t smem_u32(const void* p) {
    return (uint32_t)__cvta_generic_to_shared(p);
}
__device__ __forceinline__ void ldm_x4(uint32_t* r, uint32_t addr) {
    asm volatile("ldmatrix.sync.aligned.m8n8.x4.shared.b16 {%0,%1,%2,%3}, [%4];"
        : "=r"(r[0]), "=r"(r[1]), "=r"(r[2]), "=r"(r[3]) : "r"(addr));
}
__device__ __forceinline__ void ldm_x4_t(uint32_t* r, uint32_t addr) {
    asm volatile("ldmatrix.sync.aligned.m8n8.x4.trans.shared.b16 {%0,%1,%2,%3}, [%4];"
        : "=r"(r[0]), "=r"(r[1]), "=r"(r[2]), "=r"(r[3]) : "r"(addr));
}
__device__ __forceinline__ void mma_bf16(float* d, const uint32_t* a, const uint32_t* b) {
    asm volatile(
        "mma.sync.aligned.m16n8k16.row.col.f32.bf16.bf16.f32 "
        "{%0,%1,%2,%3}, {%4,%5,%6,%7}, {%8,%9}, {%0,%1,%2,%3};"
        : "+f"(d[0]), "+f"(d[1]), "+f"(d[2]), "+f"(d[3])
        : "r"(a[0]), "r"(a[1]), "r"(a[2]), "r"(a[3]), "r"(b[0]), "r"(b[1]));
}
__device__ __forceinline__ uint32_t pack_bf16(float x, float y) {
    __nv_bfloat162 t = __float22bfloat162_rn({x, y});
    return *(uint32_t*)&t;
}
__device__ __forceinline__ void cp16(uint32_t dst, const void* src) {
    asm volatile("cp.async.cg.shared.global [%0], [%1], 16;" :: "r"(dst), "l"(src));
}
#define CP_COMMIT() asm volatile("cp.async.commit_group;")
#define CP_WAIT(n)  asm volatile("cp.async.wait_group %0;" :: "n"(n))

/* ------------------------------------------------------------------ */
/* K0: fp32 -> bf16 convert                                            */
/* ------------------------------------------------------------------ */
__global__ void __launch_bounds__(256) f2bf_kernel(
    const float* __restrict__ in, bf16* __restrict__ out, int n)
{
    int i = (blockIdx.x*blockDim.x + threadIdx.x)*4;
    if (i < n) {
        float4 v = *(const float4*)(in + i);
        *(__nv_bfloat162*)(out + i    ) = __float22bfloat162_rn({v.x, v.y});
        *(__nv_bfloat162*)(out + i + 2) = __float22bfloat162_rn({v.z, v.w});
    }
}

/* ------------------------------------------------------------------ */
/* K1: LayerNorm over channel + transpose [B,C,N] -> [B,N,C]          */
/* ------------------------------------------------------------------ */
#define LN_SMEM ((384*33 + 32 + 32 + 8*32*2) * 4)
__global__ void __launch_bounds__(256) ln_transpose_kernel(
    const float* __restrict__ x, const float* __restrict__ w,
    const float* __restrict__ bvec,
    float* __restrict__ emb, bf16* __restrict__ xn)
{
    extern __shared__ float sm[];
    float* tile  = sm;
    float* meanv = tile + 384*33;
    float* rstdv = meanv + 32;
    float* ps    = rstdv + 32;
    float* pq    = ps + 8*32;

    const int n0 = blockIdx.x * 32;
    const int b  = blockIdx.y;
    const int tx = threadIdx.x, ty = threadIdx.y;

    float s = 0.f, q = 0.f;
    for (int c = ty; c < DIMC; c += 8) {
        float v = x[(b*DIMC + c)*NSEQ + n0 + tx];
        tile[c*33 + tx] = v;
        s += v; q += v*v;
    }
    ps[ty*32+tx] = s; pq[ty*32+tx] = q;
    __syncthreads();
    if (ty == 0) {
        float S = 0.f, Q = 0.f;
        #pragma unroll
        for (int j = 0; j < 8; ++j) { S += ps[j*32+tx]; Q += pq[j*32+tx]; }
        float mu = S * (1.f/DIMC);
        meanv[tx] = mu;
        rstdv[tx] = rsqrtf(Q*(1.f/DIMC) - mu*mu + EPSV);
    }
    __syncthreads();
    const int tid  = ty*32 + tx;
    const int base = (b*NSEQ + n0)*DIMC;
    for (int idx = tid; idx < 32*DIMC; idx += 256) {
        int nl = idx / DIMC, c = idx - nl*DIMC;
        float v = tile[c*33 + nl];
        emb[base + idx] = v;
        xn [base + idx] = __float2bfloat16((v - meanv[nl]) * rstdv[nl] * w[c] + bvec[c]);
    }
}

/* ------------------------------------------------------------------ */
/* K2: bf16 GEMM, 3-stage cp.async ring, single sync per chunk        */
/* ------------------------------------------------------------------ */
__device__ __forceinline__ float gelu_f(float x) {
    return 0.5f * x * (1.f + erff(x * 0.7071067811865475f));
}

#define ALD 40
#define BLD 136
#define ASTG (128*ALD)
#define BSTG (32*BLD)
#define GEMM_SMEM ((3*ASTG + 3*BSTG) * 2)

template<int EPI, bool OUTBF>
__global__ void __launch_bounds__(256) hgemm3_kernel(
    const bf16* __restrict__ A, const bf16* __restrict__ B,
    const float* __restrict__ bias, const float* __restrict__ res,
    void* __restrict__ Cout, int M, int K, int N)
{
    extern __shared__ char dsm[];
    bf16* As = (bf16*)dsm;
    bf16* Bs = (bf16*)(dsm + 3*ASTG*sizeof(bf16));

    const int bm = blockIdx.y * 128, bn = blockIdx.x * 128;
    const int tid  = threadIdx.x;
    const int lane = tid & 31, wid = tid >> 5;
    const int wm = wid & 1, wn = wid >> 1;

    const int arow = tid >> 1, acol = (tid & 1) * 16;
    const int brow = tid >> 3, bcol = (tid & 7) * 16;
    const bf16* Ag = A + (size_t)(bm + arow)*K + acol;
    const bf16* Bg = B + (size_t)brow*N + bn + bcol;

    const int nch = K >> 5;

    auto issue = [&](int c) {
        int stg = c - (c/3)*3;
        uint32_t ad = smem_u32(As + stg*ASTG + arow*ALD + acol);
        uint32_t bd = smem_u32(Bs + stg*BSTG + brow*BLD + bcol);
        const bf16* ag = Ag + c*32;
        const bf16* bg = Bg + (size_t)c*32*N;
        cp16(ad,      ag);
        cp16(ad + 16, ag + 8);
        cp16(bd,      bg);
        cp16(bd + 16, bg + 8);
    };

    issue(0); CP_COMMIT();
    issue(1); CP_COMMIT();

    float acc[4][4][4];
    #pragma unroll
    for (int i=0;i<4;++i)
        #pragma unroll
        for (int j=0;j<4;++j)
            #pragma unroll
            for (int u=0;u<4;++u) acc[i][j][u]=0.f;

    const int a_r = (lane & 15), a_c8 = (lane >> 4) * 8;
    const int b_k = (lane & 15), b_n8 = (lane >> 4) * 8;

    for (int c = 0; c < nch; ++c) {
        const int stg = c - (c/3)*3;
        CP_WAIT(1);
        __syncthreads();
        if (c + 2 < nch) issue(c + 2);
        CP_COMMIT();

        const bf16* Ab = As + stg*ASTG;
        const bf16* Bb = Bs + stg*BSTG;
        #pragma unroll
        for (int ks = 0; ks < 2; ++ks) {
            uint32_t af[4][4], bfr[4][2];
            #pragma unroll
            for (int mt = 0; mt < 4; ++mt) {
                int row = wm*64 + mt*16 + a_r;
                int col = ks*16 + a_c8;
                ldm_x4(af[mt], smem_u32(Ab + row*ALD + col));
            }
            #pragma unroll
            for (int np = 0; np < 2; ++np) {
                uint32_t rr[4];
                int kk = ks*16 + b_k;
                int nn = wn*32 + np*16 + b_n8;
                ldm_x4_t(rr, smem_u32(Bb + kk*BLD + nn));
                bfr[np*2  ][0]=rr[0]; bfr[np*2  ][1]=rr[1];
                bfr[np*2+1][0]=rr[2]; bfr[np*2+1][1]=rr[3];
            }
            #pragma unroll
            for (int mt = 0; mt < 4; ++mt)
                #pragma unroll
                for (int nt = 0; nt < 4; ++nt)
                    mma_bf16(acc[mt][nt], af[mt], bfr[nt]);
        }
    }

    const int g = lane >> 2, qp = lane & 3;
    #pragma unroll
    for (int mt = 0; mt < 4; ++mt) {
        #pragma unroll
        for (int half = 0; half < 2; ++half) {
            int r = bm + wm*64 + mt*16 + g + half*8;
            #pragma unroll
            for (int nt = 0; nt < 4; ++nt) {
                int cix = bn + wn*32 + nt*8 + qp*2;
                float v0 = acc[mt][nt][half*2+0];
                float v1 = acc[mt][nt][half*2+1];
                if (EPI >= 1) { v0 += bias[cix]; v1 += bias[cix+1]; }
                if (EPI == 2) { v0 = gelu_f(v0); v1 = gelu_f(v1); }
                if (EPI == 1) {
                    float2 rr = *(const float2*)(res + (size_t)r*N + cix);
                    v0 += rr.x; v1 += rr.y;
                }
                if (OUTBF) {
                    bf16* Cb = (bf16*)Cout;
                    *(uint32_t*)(Cb + (size_t)r*N + cix) = pack_bf16(v0, v1);
                } else {
                    float* Cf = (float*)Cout;
                    float2 o = {v0, v1};
                    *(float2*)(Cf + (size_t)r*N + cix) = o;
                }
            }
        }
    }
}

/* ------------------------------------------------------------------ */
/* K3: bf16 flash attention, double-buffered cp.async KV, merged      */
/* branches (grid.z = 32). SCALE folded into Q tile (exact 2^-3).     */
/* ------------------------------------------------------------------ */
#define KPAD 72

__global__ void __launch_bounds__(128) attn3_kernel(
    const bf16* __restrict__ kqv0, const bf16* __restrict__ kqv1,
    bf16* __restrict__ attn_out)
{
    __shared__ bf16 Qs[64*KPAD];
    __shared__ bf16 Ks[2][64*KPAD];
    __shared__ bf16 Vs[2][64*KPAD];

    const int qt = blockIdx.x, h = blockIdx.y;
    const int zz = blockIdx.z;
    const int br = zz >> 4, b = zz & 15;
    const bf16* kqvQ  = br ? kqv1 : kqv0;
    const bf16* kqvKV = br ? kqv0 : kqv1;
    bf16* outp = attn_out + (size_t)br * (BNTOT*DIMC);

    const int tid = threadIdx.x, lane = tid & 31, w = tid >> 5;

    const bf16* qb = kqvQ  + (size_t)(b*NSEQ + qt*64)*1152 + DIMC + h*HD;
    const bf16* kb = kqvKV + (size_t)(b*NSEQ)*1152                + h*HD;
    const bf16* vb = kqvKV + (size_t)(b*NSEQ)*1152 + 2*DIMC       + h*HD;

    /* Q tile with exact 2^-3 scaling */
    const __nv_bfloat162 sc2 = __float2bfloat162_rn(0.125f);
    for (int idx = tid; idx < 512; idx += 128) {
        int r = idx >> 3, s = (idx & 7) * 8;
        uint4 v = *(const uint4*)(qb + (size_t)r*1152 + s);
        __nv_bfloat162* h2 = (__nv_bfloat162*)&v;
        h2[0] = __hmul2(h2[0], sc2); h2[1] = __hmul2(h2[1], sc2);
        h2[2] = __hmul2(h2[2], sc2); h2[3] = __hmul2(h2[3], sc2);
        *(uint4*)&Qs[r*KPAD + s] = v;
    }

    auto issue_kv = [&](int t) {
        int buf = t & 1;
        for (int idx = tid; idx < 512; idx += 128) {
            int r = idx >> 3, s = (idx & 7) * 8;
            cp16(smem_u32(&Ks[buf][r*KPAD + s]), kb + (size_t)(t*64 + r)*1152 + s);
            cp16(smem_u32(&Vs[buf][r*KPAD + s]), vb + (size_t)(t*64 + r)*1152 + s);
        }
    };
    issue_kv(0); CP_COMMIT();
    __syncthreads();   /* Qs visible */

    const int a_r = (lane & 15), a_c8 = (lane >> 4) * 8;
    uint32_t qa[4][4];
    #pragma unroll
    for (int ks = 0; ks < 4; ++ks)
        ldm_x4(qa[ks], smem_u32(&Qs[(w*16 + a_r)*KPAD + ks*16 + a_c8]));

    float m0 = -1e30f, m1 = -1e30f, l0 = 0.f, l1 = 0.f;
    float oacc[8][4];
    #pragma unroll
    for (int i=0;i<8;++i)
        #pragma unroll
        for (int u=0;u<4;++u) oacc[i][u]=0.f;

    for (int t = 0; t < 16; ++t) {
        const int buf = t & 1;
        CP_WAIT(0);          /* tile t resident */
        __syncthreads();     /* all warps done with buf (t-1)&1 */
        if (t + 1 < 16) issue_kv(t + 1);
        CP_COMMIT();

        /* S = Q @ K^T (K natural layout, non-trans ldmatrix) */
        float sacc[8][4];
        #pragma unroll
        for (int i=0;i<8;++i)
            #pragma unroll
            for (int u=0;u<4;++u) sacc[i][u]=0.f;
        #pragma unroll
        for (int ks = 0; ks < 4; ++ks) {
            #pragma unroll
            for (int grp = 0; grp < 4; ++grp) {
                uint32_t kf[4];
                ldm_x4(kf, smem_u32(&Ks[buf][(grp*16 + a_r)*KPAD + ks*16 + a_c8]));
                uint32_t b0[2] = {kf[0], kf[2]};
                uint32_t b1[2] = {kf[1], kf[3]};
                mma_bf16(sacc[grp*2  ], qa[ks], b0);
                mma_bf16(sacc[grp*2+1], qa[ks], b1);
            }
        }

        /* online softmax */
        float rmax0 = -1e30f, rmax1 = -1e30f;
        #pragma unroll
        for (int nt = 0; nt < 8; ++nt) {
            rmax0 = fmaxf(rmax0, fmaxf(sacc[nt][0], sacc[nt][1]));
            rmax1 = fmaxf(rmax1, fmaxf(sacc[nt][2], sacc[nt][3]));
        }
        rmax0 = fmaxf(rmax0, __shfl_xor_sync(0xffffffffu, rmax0, 1));
        rmax0 = fmaxf(rmax0, __shfl_xor_sync(0xffffffffu, rmax0, 2));
        rmax1 = fmaxf(rmax1, __shfl_xor_sync(0xffffffffu, rmax1, 1));
        rmax1 = fmaxf(rmax1, __shfl_xor_sync(0xffffffffu, rmax1, 2));

        float mnew0 = fmaxf(m0, rmax0), mnew1 = fmaxf(m1, rmax1);
        float alpha0 = __expf(m0 - mnew0), alpha1 = __expf(m1 - mnew1);
        m0 = mnew0; m1 = mnew1;

        float rsum0 = 0.f, rsum1 = 0.f;
        #pragma unroll
        for (int nt = 0; nt < 8; ++nt) {
            sacc[nt][0] = __expf(sacc[nt][0] - mnew0);
            sacc[nt][1] = __expf(sacc[nt][1] - mnew0);
            sacc[nt][2] = __expf(sacc[nt][2] - mnew1);
            sacc[nt][3] = __expf(sacc[nt][3] - mnew1);
            rsum0 += sacc[nt][0] + sacc[nt][1];
            rsum1 += sacc[nt][2] + sacc[nt][3];
        }
        rsum0 += __shfl_xor_sync(0xffffffffu, rsum0, 1);
        rsum0 += __shfl_xor_sync(0xffffffffu, rsum0, 2);
        rsum1 += __shfl_xor_sync(0xffffffffu, rsum1, 1);
        rsum1 += __shfl_xor_sync(0xffffffffu, rsum1, 2);
        l0 = l0*alpha0 + rsum0;
        l1 = l1*alpha1 + rsum1;

        #pragma unroll
        for (int i=0;i<8;++i) {
            oacc[i][0] *= alpha0; oacc[i][1] *= alpha0;
            oacc[i][2] *= alpha1; oacc[i][3] *= alpha1;
        }

        /* O += P @ V */
        #pragma unroll
        for (int ks = 0; ks < 4; ++ks) {
            uint32_t pa[4];
            pa[0] = pack_bf16(sacc[2*ks  ][0], sacc[2*ks  ][1]);
            pa[1] = pack_bf16(sacc[2*ks  ][2], sacc[2*ks  ][3]);
            pa[2] = pack_bf16(sacc[2*ks+1][0], sacc[2*ks+1][1]);
            pa[3] = pack_bf16(sacc[2*ks+1][2], sacc[2*ks+1][3]);
            #pragma unroll
            for (int dg = 0; dg < 4; ++dg) {
                uint32_t vf[4];
                ldm_x4_t(vf, smem_u32(&Vs[buf][(ks*16 + a_r)*KPAD + dg*16 + a_c8]));
                mma_bf16(oacc[dg*2  ], pa, vf    );
                mma_bf16(oacc[dg*2+1], pa, vf + 2);
            }
        }
    }

    const float inv0 = 1.f / l0, inv1 = 1.f / l1;
    const int g = lane >> 2, qp = lane & 3;
    const size_t r0 = (size_t)(b*NSEQ + qt*64 + w*16 + g)*DIMC + h*HD;
    #pragma unroll
    for (int nt = 0; nt < 8; ++nt) {
        int col = nt*8 + qp*2;
        *(uint32_t*)(outp + r0 + col)          = pack_bf16(oacc[nt][0]*inv0, oacc[nt][1]*inv0);
        *(uint32_t*)(outp + r0 + 8*DIMC + col) = pack_bf16(oacc[nt][2]*inv1, oacc[nt][3]*inv1);
    }
}

/* ------------------------------------------------------------------ */
/* K4: row LayerNorm (fp32 in, bf16 out)                              */
/* ------------------------------------------------------------------ */
__global__ void __launch_bounds__(128) ln_rows_kernel(
    const float* __restrict__ in, const float* __restrict__ w,
    const float* __restrict__ bb, bf16* __restrict__ out)
{
    const int row = blockIdx.x;
    const float* p = in + (size_t)row*DIMC;
    const int tid = threadIdx.x;
    float v0 = p[tid], v1 = p[tid+128], v2 = p[tid+256];
    float s = v0+v1+v2;
    float q = v0*v0 + v1*v1 + v2*v2;
    #pragma unroll
    for (int o = 16; o; o >>= 1) {
        s += __shfl_xor_sync(0xffffffffu, s, o);
        q += __shfl_xor_sync(0xffffffffu, q, o);
    }
    __shared__ float ss[4], qq[4];
    if ((tid & 31) == 0) { ss[tid>>5] = s; qq[tid>>5] = q; }
    __syncthreads();
    s = ss[0]+ss[1]+ss[2]+ss[3];
    q = qq[0]+qq[1]+qq[2]+qq[3];
    float mu = s * (1.f/DIMC);
    float rs = rsqrtf(q*(1.f/DIMC) - mu*mu + EPSV);
    out[(size_t)row*DIMC + tid      ] = __float2bfloat16((v0-mu)*rs*w[tid      ] + bb[tid      ]);
    out[(size_t)row*DIMC + tid + 128] = __float2bfloat16((v1-mu)*rs*w[tid + 128] + bb[tid + 128]);
    out[(size_t)row*DIMC + tid + 256] = __float2bfloat16((v2-mu)*rs*w[tid + 256] + bb[tid + 256]);
}

/* ------------------------------------------------------------------ */
/* K5: transpose [B,N,C] -> [B,C,N]                                   */
/* ------------------------------------------------------------------ */
__global__ void __launch_bounds__(256) transpose_out_kernel(
    const float* __restrict__ in, float* __restrict__ outp)
{
    __shared__ float t[32][33];
    const int n0 = blockIdx.x*32, c0 = blockIdx.y*32, b = blockIdx.z;
    const int tx = threadIdx.x, ty = threadIdx.y;
    #pragma unroll
    for (int i = ty; i < 32; i += 8)
        t[i][tx] = in[(size_t)(b*NSEQ + n0+i)*DIMC + c0 + tx];
    __syncthreads();
    #pragma unroll
    for (int i = ty; i < 32; i += 8)
        outp[(size_t)(b*DIMC + c0+i)*NSEQ + n0 + tx] = t[tx][i];
}

/* ------------------------------------------------------------------ */
extern "C" void kernel_launch(void* const* d_in, const int* in_sizes, int n_in,
                              void* d_out, int out_size)
{
    (void)in_sizes; (void)n_in; (void)out_size;
    const float* x1       = (const float*)d_in[0];
    const float* x2       = (const float*)d_in[1];
    const float* ln_a1_w  = (const float*)d_in[2];
    const float* ln_a1_b  = (const float*)d_in[3];
    const float* kqv1_w   = (const float*)d_in[4];
    const float* ln_a2_w  = (const float*)d_in[5];
    const float* ln_a2_b  = (const float*)d_in[6];
    const float* kqv2_w   = (const float*)d_in[7];
    const float* proj1_w  = (const float*)d_in[8];
    const float* proj1_b  = (const float*)d_in[9];
    const float* proj2_w  = (const float*)d_in[10];
    const float* proj2_b  = (const float*)d_in[11];
    const float* ln1_w    = (const float*)d_in[12];
    const float* ln1_b    = (const float*)d_in[13];
    const float* ln2_w    = (const float*)d_in[14];
    const float* ln2_b    = (const float*)d_in[15];
    const float* m1f1_w   = (const float*)d_in[16];
    const float* m1f1_b   = (const float*)d_in[17];
    const float* m1f2_w   = (const float*)d_in[18];
    const float* m1f2_b   = (const float*)d_in[19];
    const float* m2f1_w   = (const float*)d_in[20];
    const float* m2f1_b   = (const float*)d_in[21];
    const float* m2f2_w   = (const float*)d_in[22];
    const float* m2f2_b   = (const float*)d_in[23];
    float* outp = (float*)d_out;

    float *p_emb, *p_res;
    bf16 *p_xn, *p_kqv, *p_attn, *p_h, *p_g, *p_w;
    cudaGetSymbolAddress((void**)&p_emb,  g_emb);
    cudaGetSymbolAddress((void**)&p_xn,   g_xn);
    cudaGetSymbolAddress((void**)&p_kqv,  g_kqv);
    cudaGetSymbolAddress((void**)&p_attn, g_attn);
    cudaGetSymbolAddress((void**)&p_res,  g_res);
    cudaGetSymbolAddress((void**)&p_h,    g_h);
    cudaGetSymbolAddress((void**)&p_g,    g_gbuf);
    cudaGetSymbolAddress((void**)&p_w,    g_wbf);

    cudaFuncSetAttribute(ln_transpose_kernel,
        cudaFuncAttributeMaxDynamicSharedMemorySize, LN_SMEM);
    cudaFuncSetAttribute(hgemm3_kernel<0,true>,
        cudaFuncAttributeMaxDynamicSharedMemorySize, GEMM_SMEM);
    cudaFuncSetAttribute(hgemm3_kernel<1,false>,
        cudaFuncAttributeMaxDynamicSharedMemorySize, GEMM_SMEM);
    cudaFuncSetAttribute(hgemm3_kernel<2,true>,
        cudaFuncAttributeMaxDynamicSharedMemorySize, GEMM_SMEM);

    const int OFF  = BNTOT*DIMC;
    const int KOFF = BNTOT*3*DIMC;
    const dim3 lnb(32, 8);

    bf16* w_kqv1 = p_w;
    bf16* w_kqv2 = w_kqv1 + W_KQV;
    bf16* w_pj1  = w_kqv2 + W_KQV;
    bf16* w_pj2  = w_pj1  + W_PROJ;
    bf16* w_f11  = w_pj2  + W_PROJ;
    bf16* w_f12  = w_f11  + W_FC;
    bf16* w_f21  = w_f12  + W_FC;
    bf16* w_f22  = w_f21  + W_FC;
    f2bf_kernel<<<(W_KQV/4+255)/256,  256>>>(kqv1_w,  w_kqv1, W_KQV);
    f2bf_kernel<<<(W_KQV/4+255)/256,  256>>>(kqv2_w,  w_kqv2, W_KQV);
    f2bf_kernel<<<(W_PROJ/4+255)/256, 256>>>(proj1_w, w_pj1,  W_PROJ);
    f2bf_kernel<<<(W_PROJ/4+255)/256, 256>>>(proj2_w, w_pj2,  W_PROJ);
    f2bf_kernel<<<(W_FC/4+255)/256,   256>>>(m1f1_w,  w_f11,  W_FC);
    f2bf_kernel<<<(W_FC/4+255)/256,   256>>>(m1f2_w,  w_f12,  W_FC);
    f2bf_kernel<<<(W_FC/4+255)/256,   256>>>(m2f1_w,  w_f21,  W_FC);
    f2bf_kernel<<<(W_FC/4+255)/256,   256>>>(m2f2_w,  w_f22,  W_FC);

    ln_transpose_kernel<<<dim3(32,16), lnb, LN_SMEM>>>(x1, ln_a1_w, ln_a1_b, p_emb,     p_xn);
    ln_transpose_kernel<<<dim3(32,16), lnb, LN_SMEM>>>(x2, ln_a2_w, ln_a2_b, p_emb+OFF, p_xn+OFF);

    hgemm3_kernel<0,true><<<dim3(9,128), 256, GEMM_SMEM>>>(p_xn,     w_kqv1, nullptr, nullptr, p_kqv,      BNTOT, DIMC, 3*DIMC);
    hgemm3_kernel<0,true><<<dim3(9,128), 256, GEMM_SMEM>>>(p_xn+OFF, w_kqv2, nullptr, nullptr, p_kqv+KOFF, BNTOT, DIMC, 3*DIMC);

    attn3_kernel<<<dim3(16,6,32), 128>>>(p_kqv, p_kqv+KOFF, p_attn);

    hgemm3_kernel<1,false><<<dim3(3,128),  256, GEMM_SMEM>>>(p_attn, w_pj1, proj1_b, p_emb, p_res, BNTOT, DIMC, DIMC);
    ln_rows_kernel<<<BNTOT, 128>>>(p_res, ln1_w, ln1_b, p_h);
    hgemm3_kernel<2,true ><<<dim3(12,128), 256, GEMM_SMEM>>>(p_h, w_f11, m1f1_b, nullptr, p_g, BNTOT, DIMC, HIDDEN);
    hgemm3_kernel<1,false><<<dim3(3,128),  256, GEMM_SMEM>>>(p_g, w_f12, m1f2_b, p_res, p_res, BNTOT, HIDDEN, DIMC);
    transpose_out_kernel<<<dim3(32,12,16), lnb>>>(p_res, outp);

    hgemm3_kernel<1,false><<<dim3(3,128),  256, GEMM_SMEM>>>(p_attn+OFF, w_pj2, proj2_b, p_emb+OFF, p_res+OFF, BNTOT, DIMC, DIMC);
    ln_rows_kernel<<<BNTOT, 128>>>(p_res+OFF, ln2_w, ln2_b, p_h);
    hgemm3_kernel<2,true ><<<dim3(12,128), 256, GEMM_SMEM>>>(p_h, w_f21, m2f1_b, nullptr, p_g, BNTOT, DIMC, HIDDEN);
    hgemm3_kernel<1,false><<<dim3(3,128),  256, GEMM_SMEM>>>(p_g, w_f22, m2f2_b, p_res+OFF, p_res+OFF, BNTOT, HIDDEN, DIMC);
    transpose_out_kernel<<<dim3(32,12,16), lnb>>>(p_res+OFF, outp + OFF);
}

// round 6
// speedup vs baseline: 5.1602x; 1.0070x over previous
#include <cuda_runtime.h>
#include <cuda_bf16.h>
#include <math.h>
#include <stdint.h>

#define DIMC 384
#define NSEQ 1024
#define BATCH 16
#define BNTOT (BATCH*NSEQ)
#define NHEAD 6
#define HD 64
#define HIDDEN 1536
#define EPSV 1e-5f

typedef __nv_bfloat16 bf16;

/* ------------------------------------------------------------------ */
/* scratch                                                             */
/* ------------------------------------------------------------------ */
__device__ float g_emb [2][BNTOT*DIMC];
__device__ bf16  g_xn  [2][BNTOT*DIMC];
__device__ bf16  g_kqv [2][BNTOT*3*DIMC];
__device__ bf16  g_attn[2][BNTOT*DIMC];
__device__ float g_res [2][BNTOT*DIMC];
__device__ bf16  g_h   [BNTOT*DIMC];
__device__ bf16  g_gbuf[BNTOT*HIDDEN];

#define W_KQV   (DIMC*3*DIMC)
#define W_PROJ  (DIMC*DIMC)
#define W_FC    (DIMC*HIDDEN)
__device__ bf16 g_wbf[2*W_KQV + 2*W_PROJ + 4*W_FC];

/* ------------------------------------------------------------------ */
/* PTX helpers                                                         */
/* ------------------------------------------------------------------ */
__device__ __forceinline__ uint32_t smem_u32(const void* p) {
    return (uint32_t)__cvta_generic_to_shared(p);
}
__device__ __forceinline__ void ldm_x4(uint32_t* r, uint32_t addr) {
    asm volatile("ldmatrix.sync.aligned.m8n8.x4.shared.b16 {%0,%1,%2,%3}, [%4];"
        : "=r"(r[0]), "=r"(r[1]), "=r"(r[2]), "=r"(r[3]) : "r"(addr));
}
__device__ __forceinline__ void ldm_x4_t(uint32_t* r, uint32_t addr) {
    asm volatile("ldmatrix.sync.aligned.m8n8.x4.trans.shared.b16 {%0,%1,%2,%3}, [%4];"
        : "=r"(r[0]), "=r"(r[1]), "=r"(r[2]), "=r"(r[3]) : "r"(addr));
}
__device__ __forceinline__ void mma_bf16(float* d, const uint32_t* a, const uint32_t* b) {
    asm volatile(
        "mma.sync.aligned.m16n8k16.row.col.f32.bf16.bf16.f32 "
        "{%0,%1,%2,%3}, {%4,%5,%6,%7}, {%8,%9}, {%0,%1,%2,%3};"
        : "+f"(d[0]), "+f"(d[1]), "+f"(d[2]), "+f"(d[3])
        : "r"(a[0]), "r"(a[1]), "r"(a[2]), "r"(a[3]), "r"(b[0]), "r"(b[1]));
}
__device__ __forceinline__ uint32_t pack_bf16(float x, float y) {
    __nv_bfloat162 t = __float22bfloat162_rn({x, y});
    return *(uint32_t*)&t;
}
__device__ __forceinline__ void cp16(uint32_t dst, const void* src) {
    asm volatile("cp.async.cg.shared.global [%0], [%1], 16;" :: "r"(dst), "l"(src));
}
#define CP_COMMIT() asm volatile("cp.async.commit_group;")
#define CP_WAIT(n)  asm volatile("cp.async.wait_group %0;" :: "n"(n))

/* ------------------------------------------------------------------ */
/* K0: fp32 -> bf16 convert, all 8 weights in one launch              */
/* ------------------------------------------------------------------ */
struct WSegs {
    const float* src[8];
    int off[8];
    int n[8];
};
__global__ void __launch_bounds__(256) f2bf_all_kernel(WSegs seg, bf16* __restrict__ dst)
{
    int i = (blockIdx.x*256 + threadIdx.x)*4;
    #pragma unroll
    for (int s = 0; s < 8; ++s) {
        if (i < seg.n[s]) {
            float4 v = *(const float4*)(seg.src[s] + i);
            bf16* o = dst + seg.off[s] + i;
            *(__nv_bfloat162*)(o    ) = __float22bfloat162_rn({v.x, v.y});
            *(__nv_bfloat162*)(o + 2) = __float22bfloat162_rn({v.z, v.w});
            return;
        }
        i -= seg.n[s];
    }
}

/* ------------------------------------------------------------------ */
/* K1: LayerNorm over channel + transpose [B,C,N] -> [B,N,C]          */
/* ------------------------------------------------------------------ */
#define LN_SMEM ((384*33 + 32 + 32 + 8*32*2) * 4)
__global__ void __launch_bounds__(256) ln_transpose_kernel(
    const float* __restrict__ x, const float* __restrict__ w,
    const float* __restrict__ bvec,
    float* __restrict__ emb, bf16* __restrict__ xn)
{
    extern __shared__ float sm[];
    float* tile  = sm;
    float* meanv = tile + 384*33;
    float* rstdv = meanv + 32;
    float* ps    = rstdv + 32;
    float* pq    = ps + 8*32;

    const int n0 = blockIdx.x * 32;
    const int b  = blockIdx.y;
    const int tx = threadIdx.x, ty = threadIdx.y;

    float s = 0.f, q = 0.f;
    for (int c = ty; c < DIMC; c += 8) {
        float v = x[(b*DIMC + c)*NSEQ + n0 + tx];
        tile[c*33 + tx] = v;
        s += v; q += v*v;
    }
    ps[ty*32+tx] = s; pq[ty*32+tx] = q;
    __syncthreads();
    if (ty == 0) {
        float S = 0.f, Q = 0.f;
        #pragma unroll
        for (int j = 0; j < 8; ++j) { S += ps[j*32+tx]; Q += pq[j*32+tx]; }
        float mu = S * (1.f/DIMC);
        meanv[tx] = mu;
        rstdv[tx] = rsqrtf(Q*(1.f/DIMC) - mu*mu + EPSV);
    }
    __syncthreads();
    const int tid  = ty*32 + tx;
    const int base = (b*NSEQ + n0)*DIMC;
    for (int idx = tid; idx < 32*DIMC; idx += 256) {
        int nl = idx / DIMC, c = idx - nl*DIMC;
        float v = tile[c*33 + nl];
        emb[base + idx] = v;
        xn [base + idx] = __float2bfloat16((v - meanv[nl]) * rstdv[nl] * w[c] + bvec[c]);
    }
}

/* ------------------------------------------------------------------ */
/* K2: bf16 GEMM, 3-stage cp.async ring                                */
/* EPI: 0 plain, 1 +bias+res(fp32 out), 2 +bias+GELU(bf16 out),       */
/*      3 +bias+res, transposed store to [B,C,N] output               */
/* ------------------------------------------------------------------ */
__device__ __forceinline__ float gelu_f(float x) {
    return 0.5f * x * (1.f + erff(x * 0.7071067811865475f));
}

#define ALD 40
#define BLD 136
#define ASTG (128*ALD)
#define BSTG (32*BLD)
#define GEMM_SMEM (128*132*4)   /* 67584 >= 3*(ASTG+BSTG)*2 = 56832 */

template<int EPI, bool OUTBF>
__global__ void __launch_bounds__(256) hgemm3_kernel(
    const bf16* __restrict__ A, const bf16* __restrict__ B,
    const float* __restrict__ bias, const float* __restrict__ res,
    void* __restrict__ Cout, int M, int K, int N)
{
    extern __shared__ char dsm[];
    bf16* As = (bf16*)dsm;
    bf16* Bs = (bf16*)(dsm + 3*ASTG*sizeof(bf16));

    const int bm = blockIdx.y * 128, bn = blockIdx.x * 128;
    const int tid  = threadIdx.x;
    const int lane = tid & 31, wid = tid >> 5;
    const int wm = wid & 1, wn = wid >> 1;

    const int arow = tid >> 1, acol = (tid & 1) * 16;
    const int brow = tid >> 3, bcol = (tid & 7) * 16;
    const bf16* Ag = A + (size_t)(bm + arow)*K + acol;
    const bf16* Bg = B + (size_t)brow*N + bn + bcol;

    const int nch = K >> 5;

    auto issue = [&](int c) {
        int stg = c - (c/3)*3;
        uint32_t ad = smem_u32(As + stg*ASTG + arow*ALD + acol);
        uint32_t bd = smem_u32(Bs + stg*BSTG + brow*BLD + bcol);
        const bf16* ag = Ag + c*32;
        const bf16* bg = Bg + (size_t)c*32*N;
        cp16(ad,      ag);
        cp16(ad + 16, ag + 8);
        cp16(bd,      bg);
        cp16(bd + 16, bg + 8);
    };

    issue(0); CP_COMMIT();
    issue(1); CP_COMMIT();

    float acc[4][4][4];
    #pragma unroll
    for (int i=0;i<4;++i)
        #pragma unroll
        for (int j=0;j<4;++j)
            #pragma unroll
            for (int u=0;u<4;++u) acc[i][j][u]=0.f;

    const int a_r = (lane & 15), a_c8 = (lane >> 4) * 8;
    const int b_k = (lane & 15), b_n8 = (lane >> 4) * 8;

    for (int c = 0; c < nch; ++c) {
        const int stg = c - (c/3)*3;
        CP_WAIT(1);
        __syncthreads();
        if (c + 2 < nch) issue(c + 2);
        CP_COMMIT();

        const bf16* Ab = As + stg*ASTG;
        const bf16* Bb = Bs + stg*BSTG;
        #pragma unroll
        for (int ks = 0; ks < 2; ++ks) {
            uint32_t af[4][4], bfr[4][2];
            #pragma unroll
            for (int mt = 0; mt < 4; ++mt) {
                int row = wm*64 + mt*16 + a_r;
                int col = ks*16 + a_c8;
                ldm_x4(af[mt], smem_u32(Ab + row*ALD + col));
            }
            #pragma unroll
            for (int np = 0; np < 2; ++np) {
                uint32_t rr[4];
                int kk = ks*16 + b_k;
                int nn = wn*32 + np*16 + b_n8;
                ldm_x4_t(rr, smem_u32(Bb + kk*BLD + nn));
                bfr[np*2  ][0]=rr[0]; bfr[np*2  ][1]=rr[1];
                bfr[np*2+1][0]=rr[2]; bfr[np*2+1][1]=rr[3];
            }
            #pragma unroll
            for (int mt = 0; mt < 4; ++mt)
                #pragma unroll
                for (int nt = 0; nt < 4; ++nt)
                    mma_bf16(acc[mt][nt], af[mt], bfr[nt]);
        }
    }

    const int g = lane >> 2, qp = lane & 3;

    if (EPI == 3) {
        /* bias + residual, then transposed coalesced store to [B,C,N] */
        float* tile = (float*)dsm;           /* [128 c][132] over n */
        __syncthreads();                     /* mainloop smem reads done */
        #pragma unroll
        for (int mt = 0; mt < 4; ++mt) {
            #pragma unroll
            for (int half = 0; half < 2; ++half) {
                int rl = wm*64 + mt*16 + g + half*8;         /* local n */
                int r  = bm + rl;
                #pragma unroll
                for (int nt = 0; nt < 4; ++nt) {
                    int cl = wn*32 + nt*8 + qp*2;            /* local c */
                    float v0 = acc[mt][nt][half*2+0] + bias[bn+cl];
                    float v1 = acc[mt][nt][half*2+1] + bias[bn+cl+1];
                    float2 rr = *(const float2*)(res + (size_t)r*N + bn + cl);
                    tile[(cl  )*132 + rl] = v0 + rr.x;
                    tile[(cl+1)*132 + rl] = v1 + rr.y;
                }
            }
        }
        __syncthreads();
        float* outp = (float*)Cout;
        const int b = bm >> 10, n0 = bm & 1023;
        #pragma unroll
        for (int pass = 0; pass < 16; ++pass) {
            int cl = pass*8 + (tid >> 5);
            int n4 = (lane) * 4;
            float4 v = *(float4*)(tile + cl*132 + n4);
            *(float4*)(outp + (size_t)(b*DIMC + bn + cl)*NSEQ + n0 + n4) = v;
        }
        return;
    }

    #pragma unroll
    for (int mt = 0; mt < 4; ++mt) {
        #pragma unroll
        for (int half = 0; half < 2; ++half) {
            int r = bm + wm*64 + mt*16 + g + half*8;
            #pragma unroll
            for (int nt = 0; nt < 4; ++nt) {
                int cix = bn + wn*32 + nt*8 + qp*2;
                float v0 = acc[mt][nt][half*2+0];
                float v1 = acc[mt][nt][half*2+1];
                if (EPI >= 1) { v0 += bias[cix]; v1 += bias[cix+1]; }
                if (EPI == 2) { v0 = gelu_f(v0); v1 = gelu_f(v1); }
                if (EPI == 1) {
                    float2 rr = *(const float2*)(res + (size_t)r*N + cix);
                    v0 += rr.x; v1 += rr.y;
                }
                if (OUTBF) {
                    bf16* Cb = (bf16*)Cout;
                    *(uint32_t*)(Cb + (size_t)r*N + cix) = pack_bf16(v0, v1);
                } else {
                    float* Cf = (float*)Cout;
                    float2 o = {v0, v1};
                    *(float2*)(Cf + (size_t)r*N + cix) = o;
                }
            }
        }
    }
}

/* ------------------------------------------------------------------ */
/* K3: bf16 flash attention, Br=128 (8 warps), Bc=64 double-buffered  */
/* merged branches (grid.z = 32)                                      */
/* ------------------------------------------------------------------ */
#define KPAD 72
#define ATTN_SMEM ((128*KPAD + 4*64*KPAD) * 2)   /* 55296 B */

__global__ void __launch_bounds__(256) attn4_kernel(
    const bf16* __restrict__ kqv0, const bf16* __restrict__ kqv1,
    bf16* __restrict__ attn_out)
{
    extern __shared__ char asmem[];
    bf16* Qs = (bf16*)asmem;                       /* [128][KPAD] */
    bf16* Ks = Qs + 128*KPAD;                      /* [2][64][KPAD] */
    bf16* Vs = Ks + 2*64*KPAD;                     /* [2][64][KPAD] */

    const int qt = blockIdx.x, h = blockIdx.y;
    const int zz = blockIdx.z;
    const int br = zz >> 4, b = zz & 15;
    const bf16* kqvQ  = br ? kqv1 : kqv0;
    const bf16* kqvKV = br ? kqv0 : kqv1;
    bf16* outp = attn_out + (size_t)br * (BNTOT*DIMC);

    const int tid = threadIdx.x, lane = tid & 31, w = tid >> 5;

    const bf16* qb = kqvQ  + (size_t)(b*NSEQ + qt*128)*1152 + DIMC + h*HD;
    const bf16* kb = kqvKV + (size_t)(b*NSEQ)*1152                + h*HD;
    const bf16* vb = kqvKV + (size_t)(b*NSEQ)*1152 + 2*DIMC       + h*HD;

    /* Q tile (128 rows) with exact 2^-3 scaling */
    const __nv_bfloat162 sc2 = __float2bfloat162_rn(0.125f);
    for (int idx = tid; idx < 1024; idx += 256) {
        int r = idx >> 3, s = (idx & 7) * 8;
        uint4 v = *(const uint4*)(qb + (size_t)r*1152 + s);
        __nv_bfloat162* h2 = (__nv_bfloat162*)&v;
        h2[0] = __hmul2(h2[0], sc2); h2[1] = __hmul2(h2[1], sc2);
        h2[2] = __hmul2(h2[2], sc2); h2[3] = __hmul2(h2[3], sc2);
        *(uint4*)&Qs[r*KPAD + s] = v;
    }

    auto issue_kv = [&](int t) {
        bf16* kd = Ks + (t & 1)*64*KPAD;
        bf16* vd = Vs + (t & 1)*64*KPAD;
        for (int idx = tid; idx < 512; idx += 256) {
            int r = idx >> 3, s = (idx & 7) * 8;
            cp16(smem_u32(kd + r*KPAD + s), kb + (size_t)(t*64 + r)*1152 + s);
            cp16(smem_u32(vd + r*KPAD + s), vb + (size_t)(t*64 + r)*1152 + s);
        }
    };
    issue_kv(0); CP_COMMIT();
    __syncthreads();   /* Qs visible */

    const int a_r = (lane & 15), a_c8 = (lane >> 4) * 8;
    uint32_t qa[4][4];
    #pragma unroll
    for (int ks = 0; ks < 4; ++ks)
        ldm_x4(qa[ks], smem_u32(&Qs[(w*16 + a_r)*KPAD + ks*16 + a_c8]));

    float m0 = -1e30f, m1 = -1e30f, l0 = 0.f, l1 = 0.f;
    float oacc[8][4];
    #pragma unroll
    for (int i=0;i<8;++i)
        #pragma unroll
        for (int u=0;u<4;++u) oacc[i][u]=0.f;

    for (int t = 0; t < 16; ++t) {
        const bf16* Kb = Ks + (t & 1)*64*KPAD;
        const bf16* Vb = Vs + (t & 1)*64*KPAD;
        CP_WAIT(0);
        __syncthreads();
        if (t + 1 < 16) issue_kv(t + 1);
        CP_COMMIT();

        float sacc[8][4];
        #pragma unroll
        for (int i=0;i<8;++i)
            #pragma unroll
            for (int u=0;u<4;++u) sacc[i][u]=0.f;
        #pragma unroll
        for (int ks = 0; ks < 4; ++ks) {
            #pragma unroll
            for (int grp = 0; grp < 4; ++grp) {
                uint32_t kf[4];
                ldm_x4(kf, smem_u32(Kb + (grp*16 + a_r)*KPAD + ks*16 + a_c8));
                uint32_t b0[2] = {kf[0], kf[2]};
                uint32_t b1[2] = {kf[1], kf[3]};
                mma_bf16(sacc[grp*2  ], qa[ks], b0);
                mma_bf16(sacc[grp*2+1], qa[ks], b1);
            }
        }

        float rmax0 = -1e30f, rmax1 = -1e30f;
        #pragma unroll
        for (int nt = 0; nt < 8; ++nt) {
            rmax0 = fmaxf(rmax0, fmaxf(sacc[nt][0], sacc[nt][1]));
            rmax1 = fmaxf(rmax1, fmaxf(sacc[nt][2], sacc[nt][3]));
        }
        rmax0 = fmaxf(rmax0, __shfl_xor_sync(0xffffffffu, rmax0, 1));
        rmax0 = fmaxf(rmax0, __shfl_xor_sync(0xffffffffu, rmax0, 2));
        rmax1 = fmaxf(rmax1, __shfl_xor_sync(0xffffffffu, rmax1, 1));
        rmax1 = fmaxf(rmax1, __shfl_xor_sync(0xffffffffu, rmax1, 2));

        float mnew0 = fmaxf(m0, rmax0), mnew1 = fmaxf(m1, rmax1);
        float alpha0 = __expf(m0 - mnew0), alpha1 = __expf(m1 - mnew1);
        m0 = mnew0; m1 = mnew1;

        float rsum0 = 0.f, rsum1 = 0.f;
        #pragma unroll
        for (int nt = 0; nt < 8; ++nt) {
            sacc[nt][0] = __expf(sacc[nt][0] - mnew0);
            sacc[nt][1] = __expf(sacc[nt][1] - mnew0);
            sacc[nt][2] = __expf(sacc[nt][2] - mnew1);
            sacc[nt][3] = __expf(sacc[nt][3] - mnew1);
            rsum0 += sacc[nt][0] + sacc[nt][1];
            rsum1 += sacc[nt][2] + sacc[nt][3];
        }
        rsum0 += __shfl_xor_sync(0xffffffffu, rsum0, 1);
        rsum0 += __shfl_xor_sync(0xffffffffu, rsum0, 2);
        rsum1 += __shfl_xor_sync(0xffffffffu, rsum1, 1);
        rsum1 += __shfl_xor_sync(0xffffffffu, rsum1, 2);
        l0 = l0*alpha0 + rsum0;
        l1 = l1*alpha1 + rsum1;

        #pragma unroll
        for (int i=0;i<8;++i) {
            oacc[i][0] *= alpha0; oacc[i][1] *= alpha0;
            oacc[i][2] *= alpha1; oacc[i][3] *= alpha1;
        }

        #pragma unroll
        for (int ks = 0; ks < 4; ++ks) {
            uint32_t pa[4];
            pa[0] = pack_bf16(sacc[2*ks  ][0], sacc[2*ks  ][1]);
            pa[1] = pack_bf16(sacc[2*ks  ][2], sacc[2*ks  ][3]);
            pa[2] = pack_bf16(sacc[2*ks+1][0], sacc[2*ks+1][1]);
            pa[3] = pack_bf16(sacc[2*ks+1][2], sacc[2*ks+1][3]);
            #pragma unroll
            for (int dg = 0; dg < 4; ++dg) {
                uint32_t vf[4];
                ldm_x4_t(vf, smem_u32(Vb + (ks*16 + a_r)*KPAD + dg*16 + a_c8));
                mma_bf16(oacc[dg*2  ], pa, vf    );
                mma_bf16(oacc[dg*2+1], pa, vf + 2);
            }
        }
    }

    const float inv0 = 1.f / l0, inv1 = 1.f / l1;
    const int g = lane >> 2, qp = lane & 3;
    const size_t r0 = (size_t)(b*NSEQ + qt*128 + w*16 + g)*DIMC + h*HD;
    #pragma unroll
    for (int nt = 0; nt < 8; ++nt) {
        int col = nt*8 + qp*2;
        *(uint32_t*)(outp + r0 + col)          = pack_bf16(oacc[nt][0]*inv0, oacc[nt][1]*inv0);
        *(uint32_t*)(outp + r0 + 8*DIMC + col) = pack_bf16(oacc[nt][2]*inv1, oacc[nt][3]*inv1);
    }
}

/* ------------------------------------------------------------------ */
/* K4: row LayerNorm (fp32 in, bf16 out)                              */
/* ------------------------------------------------------------------ */
__global__ void __launch_bounds__(128) ln_rows_kernel(
    const float* __restrict__ in, const float* __restrict__ w,
    const float* __restrict__ bb, bf16* __restrict__ out)
{
    const int row = blockIdx.x;
    const float* p = in + (size_t)row*DIMC;
    const int tid = threadIdx.x;
    float v0 = p[tid], v1 = p[tid+128], v2 = p[tid+256];
    float s = v0+v1+v2;
    float q = v0*v0 + v1*v1 + v2*v2;
    #pragma unroll
    for (int o = 16; o; o >>= 1) {
        s += __shfl_xor_sync(0xffffffffu, s, o);
        q += __shfl_xor_sync(0xffffffffu, q, o);
    }
    __shared__ float ss[4], qq[4];
    if ((tid & 31) == 0) { ss[tid>>5] = s; qq[tid>>5] = q; }
    __syncthreads();
    s = ss[0]+ss[1]+ss[2]+ss[3];
    q = qq[0]+qq[1]+qq[2]+qq[3];
    float mu = s * (1.f/DIMC);
    float rs = rsqrtf(q*(1.f/DIMC) - mu*mu + EPSV);
    out[(size_t)row*DIMC + tid      ] = __float2bfloat16((v0-mu)*rs*w[tid      ] + bb[tid      ]);
    out[(size_t)row*DIMC + tid + 128] = __float2bfloat16((v1-mu)*rs*w[tid + 128] + bb[tid + 128]);
    out[(size_t)row*DIMC + tid + 256] = __float2bfloat16((v2-mu)*rs*w[tid + 256] + bb[tid + 256]);
}

/* ------------------------------------------------------------------ */
extern "C" void kernel_launch(void* const* d_in, const int* in_sizes, int n_in,
                              void* d_out, int out_size)
{
    (void)in_sizes; (void)n_in; (void)out_size;
    const float* x1       = (const float*)d_in[0];
    const float* x2       = (const float*)d_in[1];
    const float* ln_a1_w  = (const float*)d_in[2];
    const float* ln_a1_b  = (const float*)d_in[3];
    const float* kqv1_w   = (const float*)d_in[4];
    const float* ln_a2_w  = (const float*)d_in[5];
    const float* ln_a2_b  = (const float*)d_in[6];
    const float* kqv2_w   = (const float*)d_in[7];
    const float* proj1_w  = (const float*)d_in[8];
    const float* proj1_b  = (const float*)d_in[9];
    const float* proj2_w  = (const float*)d_in[10];
    const float* proj2_b  = (const float*)d_in[11];
    const float* ln1_w    = (const float*)d_in[12];
    const float* ln1_b    = (const float*)d_in[13];
    const float* ln2_w    = (const float*)d_in[14];
    const float* ln2_b    = (const float*)d_in[15];
    const float* m1f1_w   = (const float*)d_in[16];
    const float* m1f1_b   = (const float*)d_in[17];
    const float* m1f2_w   = (const float*)d_in[18];
    const float* m1f2_b   = (const float*)d_in[19];
    const float* m2f1_w   = (const float*)d_in[20];
    const float* m2f1_b   = (const float*)d_in[21];
    const float* m2f2_w   = (const float*)d_in[22];
    const float* m2f2_b   = (const float*)d_in[23];
    float* outp = (float*)d_out;

    float *p_emb, *p_res;
    bf16 *p_xn, *p_kqv, *p_attn, *p_h, *p_g, *p_w;
    cudaGetSymbolAddress((void**)&p_emb,  g_emb);
    cudaGetSymbolAddress((void**)&p_xn,   g_xn);
    cudaGetSymbolAddress((void**)&p_kqv,  g_kqv);
    cudaGetSymbolAddress((void**)&p_attn, g_attn);
    cudaGetSymbolAddress((void**)&p_res,  g_res);
    cudaGetSymbolAddress((void**)&p_h,    g_h);
    cudaGetSymbolAddress((void**)&p_g,    g_gbuf);
    cudaGetSymbolAddress((void**)&p_w,    g_wbf);

    cudaFuncSetAttribute(ln_transpose_kernel,
        cudaFuncAttributeMaxDynamicSharedMemorySize, LN_SMEM);
    cudaFuncSetAttribute(hgemm3_kernel<0,true>,
        cudaFuncAttributeMaxDynamicSharedMemorySize, GEMM_SMEM);
    cudaFuncSetAttribute(hgemm3_kernel<1,false>,
        cudaFuncAttributeMaxDynamicSharedMemorySize, GEMM_SMEM);
    cudaFuncSetAttribute(hgemm3_kernel<2,true>,
        cudaFuncAttributeMaxDynamicSharedMemorySize, GEMM_SMEM);
    cudaFuncSetAttribute(hgemm3_kernel<3,false>,
        cudaFuncAttributeMaxDynamicSharedMemorySize, GEMM_SMEM);
    cudaFuncSetAttribute(attn4_kernel,
        cudaFuncAttributeMaxDynamicSharedMemorySize, ATTN_SMEM);

    const int OFF  = BNTOT*DIMC;
    const int KOFF = BNTOT*3*DIMC;
    const dim3 lnb(32, 8);

    /* bf16 weight copies (one fused launch) */
    bf16* w_kqv1 = p_w;
    bf16* w_kqv2 = w_kqv1 + W_KQV;
    bf16* w_pj1  = w_kqv2 + W_KQV;
    bf16* w_pj2  = w_pj1  + W_PROJ;
    bf16* w_f11  = w_pj2  + W_PROJ;
    bf16* w_f12  = w_f11  + W_FC;
    bf16* w_f21  = w_f12  + W_FC;
    bf16* w_f22  = w_f21  + W_FC;

    WSegs seg;
    const float* srcs[8] = {kqv1_w, kqv2_w, proj1_w, proj2_w, m1f1_w, m1f2_w, m2f1_w, m2f2_w};
    const int    lens[8] = {W_KQV, W_KQV, W_PROJ, W_PROJ, W_FC, W_FC, W_FC, W_FC};
    int off = 0;
    for (int i = 0; i < 8; ++i) {
        seg.src[i] = srcs[i];
        seg.n[i]   = lens[i];
        seg.off[i] = off;
        off += lens[i];
    }
    f2bf_all_kernel<<<off/4/256, 256>>>(seg, p_w);

    ln_transpose_kernel<<<dim3(32,16), lnb, LN_SMEM>>>(x1, ln_a1_w, ln_a1_b, p_emb,     p_xn);
    ln_transpose_kernel<<<dim3(32,16), lnb, LN_SMEM>>>(x2, ln_a2_w, ln_a2_b, p_emb+OFF, p_xn+OFF);

    hgemm3_kernel<0,true><<<dim3(9,128), 256, GEMM_SMEM>>>(p_xn,     w_kqv1, nullptr, nullptr, p_kqv,      BNTOT, DIMC, 3*DIMC);
    hgemm3_kernel<0,true><<<dim3(9,128), 256, GEMM_SMEM>>>(p_xn+OFF, w_kqv2, nullptr, nullptr, p_kqv+KOFF, BNTOT, DIMC, 3*DIMC);

    attn4_kernel<<<dim3(8,6,32), 256, ATTN_SMEM>>>(p_kqv, p_kqv+KOFF, p_attn);

    hgemm3_kernel<1,false><<<dim3(3,128),  256, GEMM_SMEM>>>(p_attn, w_pj1, proj1_b, p_emb, p_res, BNTOT, DIMC, DIMC);
    ln_rows_kernel<<<BNTOT, 128>>>(p_res, ln1_w, ln1_b, p_h);
    hgemm3_kernel<2,true ><<<dim3(12,128), 256, GEMM_SMEM>>>(p_h, w_f11, m1f1_b, nullptr, p_g, BNTOT, DIMC, HIDDEN);
    hgemm3_kernel<3,false><<<dim3(3,128),  256, GEMM_SMEM>>>(p_g, w_f12, m1f2_b, p_res, outp, BNTOT, HIDDEN, DIMC);

    hgemm3_kernel<1,false><<<dim3(3,128),  256, GEMM_SMEM>>>(p_attn+OFF, w_pj2, proj2_b, p_emb+OFF, p_res+OFF, BNTOT, DIMC, DIMC);
    ln_rows_kernel<<<BNTOT, 128>>>(p_res+OFF, ln2_w, ln2_b, p_h);
    hgemm3_kernel<2,true ><<<dim3(12,128), 256, GEMM_SMEM>>>(p_h, w_f21, m2f1_b, nullptr, p_g, BNTOT, DIMC, HIDDEN);
    hgemm3_kernel<3,false><<<dim3(3,128),  256, GEMM_SMEM>>>(p_g, w_f22, m2f2_b, p_res+OFF, outp + OFF, BNTOT, HIDDEN, DIMC);
}